// round 1
// baseline (speedup 1.0000x reference)
#include <cuda_runtime.h>
#include <math.h>

#define SUB_NO 20
#define T_NO   201
#define T_DATA 100000
#define E_NO   800
#define I_NO   200

#define FKP     204            // flipped kernel, padded to mult of 4
#define WIN     464            // per (chan,sub) window floats (456 used + pad)
#define CB_T    256            // outputs per conv block
#define CB_THREADS 64          // 4 outputs per thread
#define AGG_T   32             // t rows per aggregation tile
#define AGG_THREADS 640        // 20 warps (one per subunit)

#define AGG_SMEM  (32 * 801 * 4)
#define CONV_SMEM ((40 * WIN + 40 * FKP + SUB_NO * SUB_NO + 32) * 4)

// -------- device scratch (no allocations allowed) --------
__device__ float g_syn_e[SUB_NO * T_DATA];
__device__ float g_syn_i[SUB_NO * T_DATA];
__device__ float g_fk[2 * SUB_NO * FKP];     // [chan*20+s][u] = kern[s,chan,200-u], pad 0
__device__ int   g_elist[E_NO];
__device__ int   g_ilist[I_NO];
__device__ int   g_eoff[SUB_NO + 1];
__device__ int   g_ioff[SUB_NO + 1];

// ================= K0: setup (lists, alpha kernels, filters out) ===========
__global__ void k_setup(const float* __restrict__ Cse, const float* __restrict__ Csi,
                        const float* __restrict__ Wsyn, const float* __restrict__ Tau,
                        const float* __restrict__ Delta,
                        float* __restrict__ out_filters) {
    __shared__ int s_ae[E_NO];
    __shared__ int s_ai[I_NO];
    __shared__ int s_cnt_e[SUB_NO], s_cnt_i[SUB_NO];
    __shared__ int s_off_e[SUB_NO + 1], s_off_i[SUB_NO + 1];
    const int tid = threadIdx.x;

    for (int e = tid; e < E_NO; e += blockDim.x) {
        int a = 0;
        for (int s = 0; s < SUB_NO; s++) if (Cse[s * E_NO + e] > 0.5f) a = s;
        s_ae[e] = a;
    }
    for (int i = tid; i < I_NO; i += blockDim.x) {
        int a = 0;
        for (int s = 0; s < SUB_NO; s++) if (Csi[s * I_NO + i] > 0.5f) a = s;
        s_ai[i] = a;
    }
    __syncthreads();
    if (tid < SUB_NO) {
        int c = 0;
        for (int e = 0; e < E_NO; e++) c += (s_ae[e] == tid);
        s_cnt_e[tid] = c;
        c = 0;
        for (int i = 0; i < I_NO; i++) c += (s_ai[i] == tid);
        s_cnt_i[tid] = c;
    }
    __syncthreads();
    if (tid == 0) {
        int acc = 0;
        for (int s = 0; s < SUB_NO; s++) { s_off_e[s] = acc; acc += s_cnt_e[s]; }
        s_off_e[SUB_NO] = acc;
        acc = 0;
        for (int s = 0; s < SUB_NO; s++) { s_off_i[s] = acc; acc += s_cnt_i[s]; }
        s_off_i[SUB_NO] = acc;
    }
    __syncthreads();
    if (tid < SUB_NO) {
        int w = s_off_e[tid];
        for (int e = 0; e < E_NO; e++) if (s_ae[e] == tid) g_elist[w++] = e;
        w = s_off_i[tid];
        for (int i = 0; i < I_NO; i++) if (s_ai[i] == tid) g_ilist[w++] = i;
        g_eoff[tid] = s_off_e[tid];
        g_ioff[tid] = s_off_i[tid];
        if (tid == 0) { g_eoff[SUB_NO] = s_off_e[SUB_NO]; g_ioff[SUB_NO] = s_off_i[SUB_NO]; }
    }

    // alpha kernels: kern[s,c,t] = sum_j tt*exp(-tt)*W with tt = max(t-Delta,0)/exp(Tau)
    for (int idx = tid; idx < 2 * SUB_NO * T_NO; idx += blockDim.x) {
        int t  = idx % T_NO;
        int sc = idx / T_NO;          // row of vstack: c*20 + s
        int c  = sc / SUB_NO;
        int s  = sc % SUB_NO;
        float v = 0.f;
        #pragma unroll
        for (int j = 0; j < 2; j++) {
            float W   = Wsyn [(s * 2 + j) * 2 + c];
            float tau = Tau  [(s * 2 + j) * 2 + c];
            float dl  = Delta[(s * 2 + j) * 2 + c];
            float td  = fmaxf((float)t - dl, 0.f);
            float tt  = td * expf(-tau);
            v += tt * expf(-tt) * W;
        }
        out_filters[sc * T_NO + t] = v;
        g_fk[sc * FKP + (T_NO - 1 - t)] = v;   // flipped
    }
    for (int idx = tid; idx < 2 * SUB_NO * (FKP - T_NO); idx += blockDim.x) {
        int sc = idx / (FKP - T_NO);
        int p  = idx % (FKP - T_NO);
        g_fk[sc * FKP + T_NO + p] = 0.f;       // pad
    }
}

// ================= K1: one-hot aggregation (segmented sum) ================
__global__ void __launch_bounds__(AGG_THREADS)
k_agg(const float* __restrict__ S_e, const float* __restrict__ S_i) {
    extern __shared__ float sh[];
    const int t0  = blockIdx.x * AGG_T;
    const int tid = threadIdx.x;
    const int w   = tid >> 5;      // warp = subunit
    const int l   = tid & 31;      // lane = t within tile

    // ---- excitatory: 32 x 800 tile, row stride 801 (conflict-free both ways)
    {
        const float4* src = (const float4*)S_e;
        for (int idx = tid; idx < AGG_T * 200; idx += AGG_THREADS) {
            int r = idx / 200, c = idx - r * 200;
            float4 v = src[(size_t)(t0 + r) * 200 + c];
            float* d = &sh[r * 801 + c * 4];
            d[0] = v.x; d[1] = v.y; d[2] = v.z; d[3] = v.w;
        }
    }
    __syncthreads();
    {
        int b = g_eoff[w], e = g_eoff[w + 1];
        const float* row = &sh[l * 801];
        float acc = 0.f;
        int j = b;
        for (; j + 4 <= e; j += 4) {
            int i0 = g_elist[j], i1 = g_elist[j + 1], i2 = g_elist[j + 2], i3 = g_elist[j + 3];
            acc += row[i0]; acc += row[i1]; acc += row[i2]; acc += row[i3];
        }
        for (; j < e; j++) acc += row[g_elist[j]];
        g_syn_e[w * T_DATA + t0 + l] = acc;
    }
    __syncthreads();
    // ---- inhibitory: 32 x 200 tile, row stride 201 (9 mod 32, conflict-free)
    {
        const float4* src = (const float4*)S_i;
        for (int idx = tid; idx < AGG_T * 50; idx += AGG_THREADS) {
            int r = idx / 50, c = idx - r * 50;
            float4 v = src[(size_t)(t0 + r) * 50 + c];
            float* d = &sh[r * 201 + c * 4];
            d[0] = v.x; d[1] = v.y; d[2] = v.z; d[3] = v.w;
        }
    }
    __syncthreads();
    {
        int b = g_ioff[w], e = g_ioff[w + 1];
        const float* row = &sh[l * 201];
        float acc = 0.f;
        int j = b;
        for (; j + 4 <= e; j += 4) {
            int i0 = g_ilist[j], i1 = g_ilist[j + 1], i2 = g_ilist[j + 2], i3 = g_ilist[j + 3];
            acc += row[i0]; acc += row[i1]; acc += row[i2]; acc += row[i3];
        }
        for (; j < e; j++) acc += row[g_ilist[j]];
        g_syn_i[w * T_DATA + t0 + l] = acc;
    }
}

// ================= K2: causal grouped conv + tree recursion ================
__global__ void __launch_bounds__(CB_THREADS)
k_conv(const float* __restrict__ C_den, const float* __restrict__ W_sub,
       const float* __restrict__ Theta, const float* __restrict__ V_o,
       float* __restrict__ out_v) {
    extern __shared__ float sh[];
    float* win = sh;                    // 40 * WIN
    float* fk  = win + 40 * WIN;        // 40 * FKP
    float* cw  = fk + 40 * FKP;         // 400: C_den[s][c]*exp(W_sub[c])
    float* th  = cw + SUB_NO * SUB_NO;  // 20 (+pad)

    const int tid = threadIdx.x;
    const int t0  = blockIdx.x * CB_T;

    for (int idx = tid; idx < 40 * FKP / 4; idx += CB_THREADS)
        ((float4*)fk)[idx] = ((const float4*)g_fk)[idx];
    for (int idx = tid; idx < SUB_NO * SUB_NO; idx += CB_THREADS) {
        int c = idx % SUB_NO;
        cw[idx] = C_den[idx] * expf(W_sub[c]);
    }
    if (tid < SUB_NO) th[tid] = Theta[tid];

    // windows: win[a][j] = syn[chan][s][t0-200+j], j<456; j>=456 -> 0 pad
    for (int idx = tid; idx < 40 * (WIN / 4); idx += CB_THREADS) {
        int a = idx / (WIN / 4);
        int q = idx - a * (WIN / 4);
        int s = a % SUB_NO;
        const float* src = (a < SUB_NO) ? g_syn_e : g_syn_i;
        int tb = t0 - 200 + q * 4;
        float4 v;
        if (q * 4 >= 456) {
            v = make_float4(0.f, 0.f, 0.f, 0.f);
        } else if (tb >= 0 && tb + 3 < T_DATA) {
            v = *(const float4*)&src[s * T_DATA + tb];
        } else {
            float x[4];
            #pragma unroll
            for (int k = 0; k < 4; k++) {
                int t = tb + k;
                x[k] = (t >= 0 && t < T_DATA) ? src[s * T_DATA + t] : 0.f;
            }
            v = make_float4(x[0], x[1], x[2], x[3]);
        }
        *(float4*)&win[a * WIN + q * 4] = v;
    }
    __syncthreads();

    // conv: 4 consecutive outputs per thread, 8-float sliding window
    float sr[SUB_NO][4];
    #pragma unroll 1
    for (int s = 0; s < SUB_NO; s++) {
        float a0 = 0.f, a1 = 0.f, a2 = 0.f, a3 = 0.f;
        #pragma unroll 1
        for (int ch = 0; ch < 2; ch++) {
            const float* wp = &win[(ch * SUB_NO + s) * WIN + 4 * tid];
            const float* fp = &fk[(ch * SUB_NO + s) * FKP];
            float4 v = *(const float4*)&wp[0];
            float b0 = v.x, b1 = v.y, b2 = v.z, b3 = v.w;
            #pragma unroll
            for (int g = 0; g < 51; g++) {
                float4 kv = *(const float4*)&fp[4 * g];
                float4 nv = *(const float4*)&wp[4 * g + 4];
                a0 = fmaf(kv.x, b0, a0); a1 = fmaf(kv.x, b1, a1);
                a2 = fmaf(kv.x, b2, a2); a3 = fmaf(kv.x, b3, a3);
                a0 = fmaf(kv.y, b1, a0); a1 = fmaf(kv.y, b2, a1);
                a2 = fmaf(kv.y, b3, a2); a3 = fmaf(kv.y, nv.x, a3);
                a0 = fmaf(kv.z, b2, a0); a1 = fmaf(kv.z, b3, a1);
                a2 = fmaf(kv.z, nv.x, a2); a3 = fmaf(kv.z, nv.y, a3);
                a0 = fmaf(kv.w, b3, a0); a1 = fmaf(kv.w, nv.x, a1);
                a2 = fmaf(kv.w, nv.y, a2); a3 = fmaf(kv.w, nv.z, a3);
                b0 = nv.x; b1 = nv.y; b2 = nv.z; b3 = nv.w;
            }
        }
        sr[s][0] = a0; sr[s][1] = a1; sr[s][2] = a2; sr[s][3] = a3;
    }

    // dendritic tree recursion (literal-indexed, equals reference since
    // sub[c]=0 for c<=s at use time)
    const float wexp0 = expf(W_sub[0]);
    const float vo    = V_o[0];
    #pragma unroll 1
    for (int k = 0; k < 4; k++) {
        float sub[SUB_NO];
        #pragma unroll
        for (int s = 0; s < SUB_NO; s++) sub[s] = 0.f;
        #pragma unroll
        for (int s = SUB_NO - 1; s >= 0; s--) {
            float leaf = 0.f;
            #pragma unroll
            for (int c = s + 1; c < SUB_NO; c++)
                leaf = fmaf(cw[s * SUB_NO + c], sub[c], leaf);
            sub[s] = tanhf(sr[s][k] + leaf + th[s]);
        }
        int t = t0 + 4 * tid + k;
        if (t < T_DATA) out_v[t] = sub[0] * wexp0 + vo;
    }
}

// ============================= launch ======================================
extern "C" void kernel_launch(void* const* d_in, const int* in_sizes, int n_in,
                              void* d_out, int out_size) {
    const float* S_e   = (const float*)d_in[0];
    const float* S_i   = (const float*)d_in[1];
    const float* Cse   = (const float*)d_in[2];
    const float* Csi   = (const float*)d_in[3];
    const float* Cden  = (const float*)d_in[4];
    const float* Wsyn  = (const float*)d_in[5];
    const float* Tau   = (const float*)d_in[6];
    const float* Delta = (const float*)d_in[7];
    const float* Wsub  = (const float*)d_in[8];
    const float* Theta = (const float*)d_in[9];
    const float* Vo    = (const float*)d_in[10];
    float* out = (float*)d_out;

    cudaFuncSetAttribute(k_agg,  cudaFuncAttributeMaxDynamicSharedMemorySize, AGG_SMEM);
    cudaFuncSetAttribute(k_conv, cudaFuncAttributeMaxDynamicSharedMemorySize, CONV_SMEM);

    // output layout: [0,100000) voltage | [100000,108040) filters |
    // [108040,124040) C_syn_e | [124040,128040) C_syn_i
    k_setup<<<1, 256>>>(Cse, Csi, Wsyn, Tau, Delta, out + T_DATA);
    cudaMemcpyAsync(out + T_DATA + 2 * SUB_NO * T_NO, Cse,
                    SUB_NO * E_NO * sizeof(float), cudaMemcpyDeviceToDevice, 0);
    cudaMemcpyAsync(out + T_DATA + 2 * SUB_NO * T_NO + SUB_NO * E_NO, Csi,
                    SUB_NO * I_NO * sizeof(float), cudaMemcpyDeviceToDevice, 0);
    k_agg<<<T_DATA / AGG_T, AGG_THREADS, AGG_SMEM>>>(S_e, S_i);
    k_conv<<<(T_DATA + CB_T - 1) / CB_T, CB_THREADS, CONV_SMEM>>>(Cden, Wsub, Theta, Vo, out);
}

// round 2
// speedup vs baseline: 1.4545x; 1.4545x over previous
#include <cuda_runtime.h>
#include <math.h>

#define SUB_NO 20
#define T_NO   201
#define T_DATA 100000
#define E_NO   800
#define I_NO   200

#define FKP     204            // flipped kernel row, padded to mult of 4 (zeros at 201..203)
#define WIN     460            // per (chan,sub) window floats (456 data + 4 zero pad)
#define CB_T    256            // outputs per conv block
#define CB_THREADS 128         // 4 warps -> covers all 4 SMSPs; half0=e-chan, half1=i-chan
#define AGG_T   32             // t rows per aggregation tile
#define AGG_THREADS 640        // 20 warps (one per subunit)

#define AGG_SMEM  (32 * 801 * 4)
// win 40*460 + red 256*20 + cw 400 + th 32  (floats)
#define CONV_SMEM ((40 * WIN + CB_T * SUB_NO + SUB_NO * SUB_NO + 32) * 4)

// -------- device scratch (no allocations allowed) --------
__device__ float g_syn_e[SUB_NO * T_DATA];
__device__ float g_syn_i[SUB_NO * T_DATA];
__device__ float g_fk[2 * SUB_NO * FKP];     // [chan*20+s][u] = kern[s,chan,200-u], tail 0
__device__ int   g_elist[E_NO];
__device__ int   g_ilist[I_NO];
__device__ int   g_eoff[SUB_NO + 1];
__device__ int   g_ioff[SUB_NO + 1];

// ================= K0: setup (lists, alpha kernels, filters out) ===========
__global__ void __launch_bounds__(512)
k_setup(const float* __restrict__ Cse, const float* __restrict__ Csi,
        const float* __restrict__ Wsyn, const float* __restrict__ Tau,
        const float* __restrict__ Delta,
        float* __restrict__ out_filters) {
    __shared__ int s_ae[E_NO];
    __shared__ int s_ai[I_NO];
    __shared__ int s_cnt_e[SUB_NO], s_cnt_i[SUB_NO];
    __shared__ int s_off_e[SUB_NO + 1], s_off_i[SUB_NO + 1];
    const int tid = threadIdx.x;

    // ---- alpha kernels (independent of list build) ----
    for (int idx = tid; idx < 2 * SUB_NO * T_NO; idx += blockDim.x) {
        int t  = idx % T_NO;
        int sc = idx / T_NO;          // row of vstack: c*20 + s
        int c  = sc / SUB_NO;
        int s  = sc % SUB_NO;
        float v = 0.f;
        #pragma unroll
        for (int j = 0; j < 2; j++) {
            float W   = Wsyn [(s * 2 + j) * 2 + c];
            float tau = Tau  [(s * 2 + j) * 2 + c];
            float dl  = Delta[(s * 2 + j) * 2 + c];
            float td  = fmaxf((float)t - dl, 0.f);
            float tt  = td * expf(-tau);
            v += tt * expf(-tt) * W;
        }
        out_filters[sc * T_NO + t] = v;
        g_fk[sc * FKP + (T_NO - 1 - t)] = v;   // flipped
    }
    for (int idx = tid; idx < 2 * SUB_NO * (FKP - T_NO); idx += blockDim.x) {
        int sc = idx / (FKP - T_NO);
        int p  = idx % (FKP - T_NO);
        g_fk[sc * FKP + T_NO + p] = 0.f;       // pad
    }

    // ---- synapse -> subunit assignment ----
    if (tid < SUB_NO) { s_cnt_e[tid] = 0; s_cnt_i[tid] = 0; }
    __syncthreads();
    for (int e = tid; e < E_NO; e += blockDim.x) {
        int a = 0;
        #pragma unroll
        for (int s = 0; s < SUB_NO; s++) a += s * (Cse[s * E_NO + e] > 0.5f);
        s_ae[e] = a;
        atomicAdd(&s_cnt_e[a], 1);
    }
    for (int i = tid; i < I_NO; i += blockDim.x) {
        int a = 0;
        #pragma unroll
        for (int s = 0; s < SUB_NO; s++) a += s * (Csi[s * I_NO + i] > 0.5f);
        s_ai[i] = a;
        atomicAdd(&s_cnt_i[a], 1);
    }
    __syncthreads();
    if (tid == 0) {
        int acc = 0;
        for (int s = 0; s < SUB_NO; s++) { s_off_e[s] = acc; acc += s_cnt_e[s]; }
        s_off_e[SUB_NO] = acc;
        acc = 0;
        for (int s = 0; s < SUB_NO; s++) { s_off_i[s] = acc; acc += s_cnt_i[s]; }
        s_off_i[SUB_NO] = acc;
    }
    __syncthreads();
    // deterministic scatter: one thread per subunit, stable index order
    if (tid < SUB_NO) {
        int w = s_off_e[tid];
        for (int e = 0; e < E_NO; e++) if (s_ae[e] == tid) g_elist[w++] = e;
        w = s_off_i[tid];
        for (int i = 0; i < I_NO; i++) if (s_ai[i] == tid) g_ilist[w++] = i;
        g_eoff[tid] = s_off_e[tid];
        g_ioff[tid] = s_off_i[tid];
        if (tid == 0) { g_eoff[SUB_NO] = s_off_e[SUB_NO]; g_ioff[SUB_NO] = s_off_i[SUB_NO]; }
    }
}

// ================= K1: one-hot aggregation (segmented sum) ================
__global__ void __launch_bounds__(AGG_THREADS)
k_agg(const float* __restrict__ S_e, const float* __restrict__ S_i) {
    extern __shared__ float sh[];
    const int t0  = blockIdx.x * AGG_T;
    const int tid = threadIdx.x;
    const int w   = tid >> 5;      // warp = subunit
    const int l   = tid & 31;      // lane = t within tile

    // ---- excitatory: 32 x 800 tile, row stride 801 (conflict-free both ways)
    {
        const float4* src = (const float4*)S_e;
        for (int idx = tid; idx < AGG_T * 200; idx += AGG_THREADS) {
            int r = idx / 200, c = idx - r * 200;
            float4 v = src[(size_t)(t0 + r) * 200 + c];
            float* d = &sh[r * 801 + c * 4];
            d[0] = v.x; d[1] = v.y; d[2] = v.z; d[3] = v.w;
        }
    }
    __syncthreads();
    {
        int b = g_eoff[w], e = g_eoff[w + 1];
        const float* row = &sh[l * 801];
        float acc = 0.f;
        int j = b;
        for (; j + 4 <= e; j += 4) {
            int i0 = g_elist[j], i1 = g_elist[j + 1], i2 = g_elist[j + 2], i3 = g_elist[j + 3];
            acc += row[i0]; acc += row[i1]; acc += row[i2]; acc += row[i3];
        }
        for (; j < e; j++) acc += row[g_elist[j]];
        g_syn_e[w * T_DATA + t0 + l] = acc;
    }
    __syncthreads();
    // ---- inhibitory: 32 x 200 tile, row stride 201 (conflict-free)
    {
        const float4* src = (const float4*)S_i;
        for (int idx = tid; idx < AGG_T * 50; idx += AGG_THREADS) {
            int r = idx / 50, c = idx - r * 50;
            float4 v = src[(size_t)(t0 + r) * 50 + c];
            float* d = &sh[r * 201 + c * 4];
            d[0] = v.x; d[1] = v.y; d[2] = v.z; d[3] = v.w;
        }
    }
    __syncthreads();
    {
        int b = g_ioff[w], e = g_ioff[w + 1];
        const float* row = &sh[l * 201];
        float acc = 0.f;
        int j = b;
        for (; j + 4 <= e; j += 4) {
            int i0 = g_ilist[j], i1 = g_ilist[j + 1], i2 = g_ilist[j + 2], i3 = g_ilist[j + 3];
            acc += row[i0]; acc += row[i1]; acc += row[i2]; acc += row[i3];
        }
        for (; j < e; j++) acc += row[g_ilist[j]];
        g_syn_i[w * T_DATA + t0 + l] = acc;
    }
}

// ================= K2: causal grouped conv + tree recursion ================
// 128 threads: half 0 (tid<64) = e-channel, half 1 = i-channel.
// Each half-thread computes 4 consecutive outputs of its channel's FIR;
// halves combine through smem red[] (one barrier per subunit).
__global__ void __launch_bounds__(CB_THREADS)
k_conv(const float* __restrict__ C_den, const float* __restrict__ W_sub,
       const float* __restrict__ Theta, const float* __restrict__ V_o,
       float* __restrict__ out_v) {
    extern __shared__ float sh[];
    float* win = sh;                           // 40 * WIN
    float* red = win + 40 * WIN;               // 256 * 20 partial/combined FIR
    float* cw  = red + CB_T * SUB_NO;          // 400: C_den[s][c]*exp(W_sub[c])
    float* th  = cw + SUB_NO * SUB_NO;         // 20 (+pad)

    const int tid = threadIdx.x;
    const int t0  = blockIdx.x * CB_T;

    for (int idx = tid; idx < SUB_NO * SUB_NO; idx += CB_THREADS) {
        int c = idx % SUB_NO;
        cw[idx] = C_den[idx] * expf(W_sub[c]);
    }
    if (tid < SUB_NO) th[tid] = Theta[tid];

    // windows: win[a][j] = syn[chan][s][t0-200+j], j<456; j in [456,460) -> 0
    for (int idx = tid; idx < 40 * (WIN / 4); idx += CB_THREADS) {
        int a = idx / (WIN / 4);
        int q = idx - a * (WIN / 4);
        int s = a % SUB_NO;
        const float* src = (a < SUB_NO) ? g_syn_e : g_syn_i;
        int tb = t0 - 200 + q * 4;
        float4 v;
        if (q * 4 >= 456) {
            v = make_float4(0.f, 0.f, 0.f, 0.f);
        } else if (tb >= 0 && tb + 3 < T_DATA) {
            v = *(const float4*)&src[s * T_DATA + tb];
        } else {
            float x[4];
            #pragma unroll
            for (int k = 0; k < 4; k++) {
                int t = tb + k;
                x[k] = (t >= 0 && t < T_DATA) ? src[s * T_DATA + t] : 0.f;
            }
            v = make_float4(x[0], x[1], x[2], x[3]);
        }
        *(float4*)&win[a * WIN + q * 4] = v;
    }
    __syncthreads();

    const int half = tid >> 6;       // 0 = e-channel, 1 = i-channel
    const int tl   = tid & 63;       // 64 threads x 4 outputs = 256 outputs

    #pragma unroll 1
    for (int s = 0; s < SUB_NO; s++) {
        const float* wp = &win[(half * SUB_NO + s) * WIN + 4 * tl];
        const float* fp = &g_fk[(half * SUB_NO + s) * FKP];
        float a0 = 0.f, a1 = 0.f, a2 = 0.f, a3 = 0.f;
        float4 v = *(const float4*)&wp[0];
        float b0 = v.x, b1 = v.y, b2 = v.z, b3 = v.w;
        #pragma unroll
        for (int g = 0; g < 51; g++) {
            float4 kv = __ldg((const float4*)&fp[4 * g]);     // warp-uniform, L1-hot
            float4 nv = *(const float4*)&wp[4 * g + 4];
            a0 = fmaf(kv.x, b0, a0); a1 = fmaf(kv.x, b1, a1);
            a2 = fmaf(kv.x, b2, a2); a3 = fmaf(kv.x, b3, a3);
            a0 = fmaf(kv.y, b1, a0); a1 = fmaf(kv.y, b2, a1);
            a2 = fmaf(kv.y, b3, a2); a3 = fmaf(kv.y, nv.x, a3);
            a0 = fmaf(kv.z, b2, a0); a1 = fmaf(kv.z, b3, a1);
            a2 = fmaf(kv.z, nv.x, a2); a3 = fmaf(kv.z, nv.y, a3);
            a0 = fmaf(kv.w, b3, a0); a1 = fmaf(kv.w, nv.x, a1);
            a2 = fmaf(kv.w, nv.y, a2); a3 = fmaf(kv.w, nv.z, a3);
            b0 = nv.x; b1 = nv.y; b2 = nv.z; b3 = nv.w;
        }
        // combine halves: half0 stores, barrier, half1 accumulates.
        if (half == 0) {
            red[(4 * tl + 0) * SUB_NO + s] = a0;
            red[(4 * tl + 1) * SUB_NO + s] = a1;
            red[(4 * tl + 2) * SUB_NO + s] = a2;
            red[(4 * tl + 3) * SUB_NO + s] = a3;
        }
        __syncthreads();
        if (half == 1) {
            red[(4 * tl + 0) * SUB_NO + s] += a0;
            red[(4 * tl + 1) * SUB_NO + s] += a1;
            red[(4 * tl + 2) * SUB_NO + s] += a2;
            red[(4 * tl + 3) * SUB_NO + s] += a3;
        }
        // no second barrier needed: next iteration writes different cells;
        // final reads are after the loop-exit barrier below.
    }
    __syncthreads();

    // dendritic tree recursion: 2 outputs per thread (o = tid, tid+128)
    const float wexp0 = expf(W_sub[0]);
    const float vo    = V_o[0];
    #pragma unroll 1
    for (int r = 0; r < 2; r++) {
        int o = tid + 128 * r;
        int t = t0 + o;
        float sub[SUB_NO];
        #pragma unroll
        for (int s = 0; s < SUB_NO; s++) sub[s] = 0.f;
        #pragma unroll
        for (int s = SUB_NO - 1; s >= 0; s--) {
            float leaf = 0.f;
            #pragma unroll
            for (int c = s + 1; c < SUB_NO; c++)
                leaf = fmaf(cw[s * SUB_NO + c], sub[c], leaf);
            sub[s] = tanhf(red[o * SUB_NO + s] + leaf + th[s]);
        }
        if (t < T_DATA) out_v[t] = sub[0] * wexp0 + vo;
    }
}

// ============================= launch ======================================
extern "C" void kernel_launch(void* const* d_in, const int* in_sizes, int n_in,
                              void* d_out, int out_size) {
    const float* S_e   = (const float*)d_in[0];
    const float* S_i   = (const float*)d_in[1];
    const float* Cse   = (const float*)d_in[2];
    const float* Csi   = (const float*)d_in[3];
    const float* Cden  = (const float*)d_in[4];
    const float* Wsyn  = (const float*)d_in[5];
    const float* Tau   = (const float*)d_in[6];
    const float* Delta = (const float*)d_in[7];
    const float* Wsub  = (const float*)d_in[8];
    const float* Theta = (const float*)d_in[9];
    const float* Vo    = (const float*)d_in[10];
    float* out = (float*)d_out;

    cudaFuncSetAttribute(k_agg,  cudaFuncAttributeMaxDynamicSharedMemorySize, AGG_SMEM);
    cudaFuncSetAttribute(k_conv, cudaFuncAttributeMaxDynamicSharedMemorySize, CONV_SMEM);

    // output layout: [0,100000) voltage | [100000,108040) filters |
    // [108040,124040) C_syn_e | [124040,128040) C_syn_i
    k_setup<<<1, 512>>>(Cse, Csi, Wsyn, Tau, Delta, out + T_DATA);
    cudaMemcpyAsync(out + T_DATA + 2 * SUB_NO * T_NO, Cse,
                    SUB_NO * E_NO * sizeof(float), cudaMemcpyDeviceToDevice, 0);
    cudaMemcpyAsync(out + T_DATA + 2 * SUB_NO * T_NO + SUB_NO * E_NO, Csi,
                    SUB_NO * I_NO * sizeof(float), cudaMemcpyDeviceToDevice, 0);
    k_agg<<<T_DATA / AGG_T, AGG_THREADS, AGG_SMEM>>>(S_e, S_i);
    k_conv<<<(T_DATA + CB_T - 1) / CB_T, CB_THREADS, CONV_SMEM>>>(Cden, Wsub, Theta, Vo, out);
}

// round 3
// speedup vs baseline: 2.0332x; 1.3978x over previous
#include <cuda_runtime.h>
#include <math.h>

#define SUB_NO 20
#define T_NO   201
#define T_DATA 100000
#define E_NO   800
#define I_NO   200

#define FKP     204            // flipped kernel row, padded to mult of 4 (zeros at 201..203)
#define AGG_T   32             // t rows per aggregation tile
#define AGG_THREADS 640        // 20 warps (one per subunit)

#define FIR_T    512           // outputs per fir block
#define FIR_THREADS 128        // 4 outputs/thread
#define FIR_WIN  716           // 512 + 200 halo + 4 pad (float4 multiple: 179 vec4)
#define FIR_CHUNKS ((T_DATA + FIR_T - 1) / FIR_T)   // 196

#define TREE_THREADS 256

#define AGG_SMEM  (32 * 801 * 4)
#define FIR_SMEM  ((2 * FIR_WIN + 2 * FKP) * 4)

// -------- device scratch (no allocations allowed) --------
__device__ float g_syn_e[SUB_NO * T_DATA];
__device__ float g_syn_i[SUB_NO * T_DATA];
__device__ float g_fir[SUB_NO * T_DATA];
__device__ float g_fk[2 * SUB_NO * FKP];     // [chan*20+s][u] = kern[s,chan,200-u], tail 0
__device__ int   g_elist[E_NO];
__device__ int   g_ilist[I_NO];
__device__ int   g_eoff[SUB_NO + 1];
__device__ int   g_ioff[SUB_NO + 1];

// ================= K0: setup (lists, alpha kernels, filters out) ===========
__global__ void __launch_bounds__(512)
k_setup(const float* __restrict__ Cse, const float* __restrict__ Csi,
        const float* __restrict__ Wsyn, const float* __restrict__ Tau,
        const float* __restrict__ Delta,
        float* __restrict__ out_filters) {
    __shared__ int s_ae[E_NO];
    __shared__ int s_ai[I_NO];
    __shared__ int s_cnt_e[SUB_NO], s_cnt_i[SUB_NO];
    __shared__ int s_off_e[SUB_NO + 1], s_off_i[SUB_NO + 1];
    const int tid = threadIdx.x;

    // ---- alpha kernels ----
    for (int idx = tid; idx < 2 * SUB_NO * T_NO; idx += blockDim.x) {
        int t  = idx % T_NO;
        int sc = idx / T_NO;          // row of vstack: c*20 + s
        int c  = sc / SUB_NO;
        int s  = sc % SUB_NO;
        float v = 0.f;
        #pragma unroll
        for (int j = 0; j < 2; j++) {
            float W   = Wsyn [(s * 2 + j) * 2 + c];
            float tau = Tau  [(s * 2 + j) * 2 + c];
            float dl  = Delta[(s * 2 + j) * 2 + c];
            float td  = fmaxf((float)t - dl, 0.f);
            float tt  = td * expf(-tau);
            v += tt * expf(-tt) * W;
        }
        out_filters[sc * T_NO + t] = v;
        g_fk[sc * FKP + (T_NO - 1 - t)] = v;   // flipped
    }
    for (int idx = tid; idx < 2 * SUB_NO * (FKP - T_NO); idx += blockDim.x) {
        int sc = idx / (FKP - T_NO);
        int p  = idx % (FKP - T_NO);
        g_fk[sc * FKP + T_NO + p] = 0.f;       // pad
    }

    // ---- assignments + counts ----
    if (tid < SUB_NO) { s_cnt_e[tid] = 0; s_cnt_i[tid] = 0; }
    __syncthreads();
    for (int e = tid; e < E_NO; e += blockDim.x) {
        int a = 0;
        #pragma unroll
        for (int s = 0; s < SUB_NO; s++) a += s * (Cse[s * E_NO + e] > 0.5f);
        s_ae[e] = a;
        atomicAdd(&s_cnt_e[a], 1);
    }
    for (int i = tid; i < I_NO; i += blockDim.x) {
        int a = 0;
        #pragma unroll
        for (int s = 0; s < SUB_NO; s++) a += s * (Csi[s * I_NO + i] > 0.5f);
        s_ai[i] = a;
        atomicAdd(&s_cnt_i[a], 1);
    }
    __syncthreads();
    if (tid == 0) {
        int acc = 0;
        for (int s = 0; s < SUB_NO; s++) { s_off_e[s] = acc; acc += s_cnt_e[s]; }
        s_off_e[SUB_NO] = acc;
        acc = 0;
        for (int s = 0; s < SUB_NO; s++) { s_off_i[s] = acc; acc += s_cnt_i[s]; }
        s_off_i[SUB_NO] = acc;
    }
    __syncthreads();
    // ---- deterministic parallel scatter via rank ----
    for (int e = tid; e < E_NO; e += blockDim.x) {
        int a = s_ae[e], r = 0;
        for (int p = 0; p < e; p++) r += (s_ae[p] == a);
        g_elist[s_off_e[a] + r] = e;
    }
    for (int i = tid; i < I_NO; i += blockDim.x) {
        int a = s_ai[i], r = 0;
        for (int p = 0; p < i; p++) r += (s_ai[p] == a);
        g_ilist[s_off_i[a] + r] = i;
    }
    if (tid <= SUB_NO) { g_eoff[tid] = s_off_e[tid]; g_ioff[tid] = s_off_i[tid]; }
}

// ================= K1: one-hot aggregation (segmented sum) ================
__global__ void __launch_bounds__(AGG_THREADS)
k_agg(const float* __restrict__ S_e, const float* __restrict__ S_i) {
    extern __shared__ float sh[];
    const int t0  = blockIdx.x * AGG_T;
    const int tid = threadIdx.x;
    const int w   = tid >> 5;      // warp = subunit
    const int l   = tid & 31;      // lane = t within tile

    // ---- excitatory: 32 x 800 tile, row stride 801 (conflict-free both ways)
    {
        const float4* src = (const float4*)S_e;
        for (int idx = tid; idx < AGG_T * 200; idx += AGG_THREADS) {
            int r = idx / 200, c = idx - r * 200;
            float4 v = src[(size_t)(t0 + r) * 200 + c];
            float* d = &sh[r * 801 + c * 4];
            d[0] = v.x; d[1] = v.y; d[2] = v.z; d[3] = v.w;
        }
    }
    __syncthreads();
    {
        int b = g_eoff[w], e = g_eoff[w + 1];
        const float* row = &sh[l * 801];
        float acc = 0.f;
        int j = b;
        for (; j + 4 <= e; j += 4) {
            int i0 = g_elist[j], i1 = g_elist[j + 1], i2 = g_elist[j + 2], i3 = g_elist[j + 3];
            acc += row[i0]; acc += row[i1]; acc += row[i2]; acc += row[i3];
        }
        for (; j < e; j++) acc += row[g_elist[j]];
        g_syn_e[w * T_DATA + t0 + l] = acc;
    }
    __syncthreads();
    // ---- inhibitory: 32 x 200 tile, row stride 201 (conflict-free)
    {
        const float4* src = (const float4*)S_i;
        for (int idx = tid; idx < AGG_T * 50; idx += AGG_THREADS) {
            int r = idx / 50, c = idx - r * 50;
            float4 v = src[(size_t)(t0 + r) * 50 + c];
            float* d = &sh[r * 201 + c * 4];
            d[0] = v.x; d[1] = v.y; d[2] = v.z; d[3] = v.w;
        }
    }
    __syncthreads();
    {
        int b = g_ioff[w], e = g_ioff[w + 1];
        const float* row = &sh[l * 201];
        float acc = 0.f;
        int j = b;
        for (; j + 4 <= e; j += 4) {
            int i0 = g_ilist[j], i1 = g_ilist[j + 1], i2 = g_ilist[j + 2], i3 = g_ilist[j + 3];
            acc += row[i0]; acc += row[i1]; acc += row[i2]; acc += row[i3];
        }
        for (; j < e; j++) acc += row[g_ilist[j]];
        g_syn_i[w * T_DATA + t0 + l] = acc;
    }
}

// ================= K2: grouped causal FIR, one (subunit, chunk) per block ==
// block = 128 threads, 512 outputs. Both channels accumulate into the same
// registers: g_fir[s][t] = (syn_e[s] * ke[s])(t) + (syn_i[s] * ki[s])(t).
__global__ void __launch_bounds__(FIR_THREADS)
k_fir(void) {
    extern __shared__ float sh[];
    float* win = sh;                 // 2 * FIR_WIN  (e then i window)
    float* fk  = win + 2 * FIR_WIN;  // 2 * FKP

    const int s   = blockIdx.x % SUB_NO;
    const int t0  = (blockIdx.x / SUB_NO) * FIR_T;
    const int tid = threadIdx.x;

    // stage filters (e and i rows for this subunit)
    for (int q = tid; q < 2 * FKP / 4; q += FIR_THREADS) {
        int ch = q / (FKP / 4), r = q % (FKP / 4);
        ((float4*)&fk[ch * FKP])[r] = ((const float4*)&g_fk[(ch * SUB_NO + s) * FKP])[r];
    }

    // stage windows: win[ch][j] = syn[ch][s][t0-200+j], 0 outside [0,T_DATA)
    for (int q = tid; q < 2 * (FIR_WIN / 4); q += FIR_THREADS) {
        int ch = q / (FIR_WIN / 4), r = q % (FIR_WIN / 4);
        const float* src = ch ? g_syn_i : g_syn_e;
        int tb = t0 - 200 + 4 * r;       // multiple of 4
        float4 v;
        if (tb >= 0 && tb + 3 < T_DATA) {
            v = *(const float4*)&src[s * T_DATA + tb];
        } else {
            float x[4];
            #pragma unroll
            for (int k = 0; k < 4; k++) {
                int t = tb + k;
                x[k] = (t >= 0 && t < T_DATA) ? src[s * T_DATA + t] : 0.f;
            }
            v = make_float4(x[0], x[1], x[2], x[3]);
        }
        *(float4*)&win[ch * FIR_WIN + 4 * r] = v;
    }
    __syncthreads();

    float a0 = 0.f, a1 = 0.f, a2 = 0.f, a3 = 0.f;
    #pragma unroll 1
    for (int ch = 0; ch < 2; ch++) {
        const float* wp = &win[ch * FIR_WIN + 4 * tid];
        const float* fp = &fk[ch * FKP];
        float4 v = *(const float4*)&wp[0];
        float b0 = v.x, b1 = v.y, b2 = v.z, b3 = v.w;
        #pragma unroll
        for (int g = 0; g < 51; g++) {
            float4 kv = *(const float4*)&fp[4 * g];       // broadcast LDS
            float4 nv = *(const float4*)&wp[4 * g + 4];
            a0 = fmaf(kv.x, b0, a0); a1 = fmaf(kv.x, b1, a1);
            a2 = fmaf(kv.x, b2, a2); a3 = fmaf(kv.x, b3, a3);
            a0 = fmaf(kv.y, b1, a0); a1 = fmaf(kv.y, b2, a1);
            a2 = fmaf(kv.y, b3, a2); a3 = fmaf(kv.y, nv.x, a3);
            a0 = fmaf(kv.z, b2, a0); a1 = fmaf(kv.z, b3, a1);
            a2 = fmaf(kv.z, nv.x, a2); a3 = fmaf(kv.z, nv.y, a3);
            a0 = fmaf(kv.w, b3, a0); a1 = fmaf(kv.w, nv.x, a1);
            a2 = fmaf(kv.w, nv.y, a2); a3 = fmaf(kv.w, nv.z, a3);
            b0 = nv.x; b1 = nv.y; b2 = nv.z; b3 = nv.w;
        }
    }
    int t = t0 + 4 * tid;
    if (t + 3 < T_DATA) {
        *(float4*)&g_fir[s * T_DATA + t] = make_float4(a0, a1, a2, a3);
    } else {
        float a[4] = {a0, a1, a2, a3};
        #pragma unroll
        for (int k = 0; k < 4; k++)
            if (t + k < T_DATA) g_fir[s * T_DATA + t + k] = a[k];
    }
}

// ================= K3: dendritic tree recursion ===========================
__global__ void __launch_bounds__(TREE_THREADS)
k_tree(const float* __restrict__ C_den, const float* __restrict__ W_sub,
       const float* __restrict__ Theta, const float* __restrict__ V_o,
       float* __restrict__ out_v) {
    __shared__ float cw[SUB_NO * SUB_NO];
    __shared__ float th[SUB_NO];
    const int tid = threadIdx.x;
    for (int idx = tid; idx < SUB_NO * SUB_NO; idx += TREE_THREADS) {
        int c = idx % SUB_NO;
        cw[idx] = C_den[idx] * expf(W_sub[c]);
    }
    if (tid < SUB_NO) th[tid] = Theta[tid];
    __syncthreads();

    const int t = blockIdx.x * TREE_THREADS + tid;
    if (t >= T_DATA) return;

    float f[SUB_NO];
    #pragma unroll
    for (int s = 0; s < SUB_NO; s++) f[s] = g_fir[s * T_DATA + t];

    float sub[SUB_NO];
    #pragma unroll
    for (int s = 0; s < SUB_NO; s++) sub[s] = 0.f;
    #pragma unroll
    for (int s = SUB_NO - 1; s >= 0; s--) {
        float leaf = 0.f;
        #pragma unroll
        for (int c = s + 1; c < SUB_NO; c++)
            leaf = fmaf(cw[s * SUB_NO + c], sub[c], leaf);
        sub[s] = tanhf(f[s] + leaf + th[s]);
    }
    out_v[t] = sub[0] * expf(W_sub[0]) + V_o[0];
}

// ============================= launch ======================================
extern "C" void kernel_launch(void* const* d_in, const int* in_sizes, int n_in,
                              void* d_out, int out_size) {
    const float* S_e   = (const float*)d_in[0];
    const float* S_i   = (const float*)d_in[1];
    const float* Cse   = (const float*)d_in[2];
    const float* Csi   = (const float*)d_in[3];
    const float* Cden  = (const float*)d_in[4];
    const float* Wsyn  = (const float*)d_in[5];
    const float* Tau   = (const float*)d_in[6];
    const float* Delta = (const float*)d_in[7];
    const float* Wsub  = (const float*)d_in[8];
    const float* Theta = (const float*)d_in[9];
    const float* Vo    = (const float*)d_in[10];
    float* out = (float*)d_out;

    cudaFuncSetAttribute(k_agg, cudaFuncAttributeMaxDynamicSharedMemorySize, AGG_SMEM);
    cudaFuncSetAttribute(k_fir, cudaFuncAttributeMaxDynamicSharedMemorySize, FIR_SMEM);

    // output layout: [0,100000) voltage | [100000,108040) filters |
    // [108040,124040) C_syn_e | [124040,128040) C_syn_i
    k_setup<<<1, 512>>>(Cse, Csi, Wsyn, Tau, Delta, out + T_DATA);
    k_agg<<<T_DATA / AGG_T, AGG_THREADS, AGG_SMEM>>>(S_e, S_i);
    k_fir<<<SUB_NO * FIR_CHUNKS, FIR_THREADS, FIR_SMEM>>>();
    k_tree<<<(T_DATA + TREE_THREADS - 1) / TREE_THREADS, TREE_THREADS>>>(
        Cden, Wsub, Theta, Vo, out);
    cudaMemcpyAsync(out + T_DATA + 2 * SUB_NO * T_NO, Cse,
                    SUB_NO * E_NO * sizeof(float), cudaMemcpyDeviceToDevice, 0);
    cudaMemcpyAsync(out + T_DATA + 2 * SUB_NO * T_NO + SUB_NO * E_NO, Csi,
                    SUB_NO * I_NO * sizeof(float), cudaMemcpyDeviceToDevice, 0);
}

// round 5
// speedup vs baseline: 2.1169x; 1.0412x over previous
#include <cuda_runtime.h>
#include <math.h>

#define SUB_NO 20
#define T_NO   201
#define T_DATA 100000
#define E_NO   800
#define I_NO   200

#define FKP     208            // flipped kernel row, padded (zeros at 201..207)
#define NGROUP  52             // FKP/4 tap groups
#define AGG_T   32             // t rows per aggregation tile
#define AGG_THREADS 640        // 20 warps (one per subunit)

#define FIR_T    1024          // outputs per fir block
#define FIR_THREADS 128        // 8 outputs/thread
#define FIR_WIN  1232          // 1024 + 200 halo + 8 pad (308 float4)
#define FIR_CHUNKS ((T_DATA + FIR_T - 1) / FIR_T)   // 98

#define TREE_THREADS 256
#define T_HALF (T_DATA / 2)

#define AGG_SMEM  (32 * 801 * 4)
#define FIR_SMEM  ((2 * FIR_WIN + 2 * FKP) * 4)

// -------- device scratch (no allocations allowed) --------
__device__ float g_syn_e[SUB_NO * T_DATA];
__device__ float g_syn_i[SUB_NO * T_DATA];
__device__ float g_fir[SUB_NO * T_DATA];
__device__ float g_fk[2 * SUB_NO * FKP];     // [chan*20+s][u] = kern[s,chan,200-u], tail 0
__device__ int   g_elist[E_NO];
__device__ int   g_ilist[I_NO];
__device__ int   g_eoff[SUB_NO + 1];
__device__ int   g_ioff[SUB_NO + 1];

// ================= K0: setup (lists, alpha kernels, filters out) ===========
__global__ void __launch_bounds__(512)
k_setup(const float* __restrict__ Cse, const float* __restrict__ Csi,
        const float* __restrict__ Wsyn, const float* __restrict__ Tau,
        const float* __restrict__ Delta,
        float* __restrict__ out_filters) {
    __shared__ int s_ae[E_NO];
    __shared__ int s_ai[I_NO];
    __shared__ int s_cnt_e[SUB_NO], s_cnt_i[SUB_NO];
    __shared__ int s_off_e[SUB_NO + 1], s_off_i[SUB_NO + 1];
    const int tid = threadIdx.x;

    // ---- alpha kernels ----
    for (int idx = tid; idx < 2 * SUB_NO * T_NO; idx += blockDim.x) {
        int t  = idx % T_NO;
        int sc = idx / T_NO;          // row of vstack: c*20 + s
        int c  = sc / SUB_NO;
        int s  = sc % SUB_NO;
        float v = 0.f;
        #pragma unroll
        for (int j = 0; j < 2; j++) {
            float W   = Wsyn [(s * 2 + j) * 2 + c];
            float tau = Tau  [(s * 2 + j) * 2 + c];
            float dl  = Delta[(s * 2 + j) * 2 + c];
            float td  = fmaxf((float)t - dl, 0.f);
            float tt  = td * expf(-tau);
            v += tt * expf(-tt) * W;
        }
        out_filters[sc * T_NO + t] = v;
        g_fk[sc * FKP + (T_NO - 1 - t)] = v;   // flipped
    }
    for (int idx = tid; idx < 2 * SUB_NO * (FKP - T_NO); idx += blockDim.x) {
        int sc = idx / (FKP - T_NO);
        int p  = idx % (FKP - T_NO);
        g_fk[sc * FKP + T_NO + p] = 0.f;       // pad
    }

    // ---- assignments + counts ----
    if (tid < SUB_NO) { s_cnt_e[tid] = 0; s_cnt_i[tid] = 0; }
    __syncthreads();
    for (int e = tid; e < E_NO; e += blockDim.x) {
        int a = 0;
        #pragma unroll
        for (int s = 0; s < SUB_NO; s++) a += s * (Cse[s * E_NO + e] > 0.5f);
        s_ae[e] = a;
        atomicAdd(&s_cnt_e[a], 1);
    }
    for (int i = tid; i < I_NO; i += blockDim.x) {
        int a = 0;
        #pragma unroll
        for (int s = 0; s < SUB_NO; s++) a += s * (Csi[s * I_NO + i] > 0.5f);
        s_ai[i] = a;
        atomicAdd(&s_cnt_i[a], 1);
    }
    __syncthreads();
    if (tid == 0) {
        int acc = 0;
        for (int s = 0; s < SUB_NO; s++) { s_off_e[s] = acc; acc += s_cnt_e[s]; }
        s_off_e[SUB_NO] = acc;
        acc = 0;
        for (int s = 0; s < SUB_NO; s++) { s_off_i[s] = acc; acc += s_cnt_i[s]; }
        s_off_i[SUB_NO] = acc;
    }
    __syncthreads();
    // ---- deterministic parallel scatter via rank ----
    for (int e = tid; e < E_NO; e += blockDim.x) {
        int a = s_ae[e], r = 0;
        for (int p = 0; p < e; p++) r += (s_ae[p] == a);
        g_elist[s_off_e[a] + r] = e;
    }
    for (int i = tid; i < I_NO; i += blockDim.x) {
        int a = s_ai[i], r = 0;
        for (int p = 0; p < i; p++) r += (s_ai[p] == a);
        g_ilist[s_off_i[a] + r] = i;
    }
    if (tid <= SUB_NO) { g_eoff[tid] = s_off_e[tid]; g_ioff[tid] = s_off_i[tid]; }
}

// ================= K1: one-hot aggregation (segmented sum) ================
__global__ void __launch_bounds__(AGG_THREADS)
k_agg(const float* __restrict__ S_e, const float* __restrict__ S_i) {
    extern __shared__ float sh[];
    const int t0  = blockIdx.x * AGG_T;
    const int tid = threadIdx.x;
    const int w   = tid >> 5;      // warp = subunit
    const int l   = tid & 31;      // lane = t within tile

    // ---- excitatory: 32 x 800 tile, row stride 801 (conflict-free both ways)
    {
        const float4* src = (const float4*)S_e;
        for (int idx = tid; idx < AGG_T * 200; idx += AGG_THREADS) {
            int r = idx / 200, c = idx - r * 200;
            float4 v = src[(size_t)(t0 + r) * 200 + c];
            float* d = &sh[r * 801 + c * 4];
            d[0] = v.x; d[1] = v.y; d[2] = v.z; d[3] = v.w;
        }
    }
    __syncthreads();
    {
        int b = g_eoff[w], e = g_eoff[w + 1];
        const float* row = &sh[l * 801];
        float acc = 0.f;
        int j = b;
        for (; j + 4 <= e; j += 4) {
            int i0 = g_elist[j], i1 = g_elist[j + 1], i2 = g_elist[j + 2], i3 = g_elist[j + 3];
            acc += row[i0]; acc += row[i1]; acc += row[i2]; acc += row[i3];
        }
        for (; j < e; j++) acc += row[g_elist[j]];
        g_syn_e[w * T_DATA + t0 + l] = acc;
    }
    __syncthreads();
    // ---- inhibitory: 32 x 200 tile, row stride 201 (conflict-free)
    {
        const float4* src = (const float4*)S_i;
        for (int idx = tid; idx < AGG_T * 50; idx += AGG_THREADS) {
            int r = idx / 50, c = idx - r * 50;
            float4 v = src[(size_t)(t0 + r) * 50 + c];
            float* d = &sh[r * 201 + c * 4];
            d[0] = v.x; d[1] = v.y; d[2] = v.z; d[3] = v.w;
        }
    }
    __syncthreads();
    {
        int b = g_ioff[w], e = g_ioff[w + 1];
        const float* row = &sh[l * 201];
        float acc = 0.f;
        int j = b;
        for (; j + 4 <= e; j += 4) {
            int i0 = g_ilist[j], i1 = g_ilist[j + 1], i2 = g_ilist[j + 2], i3 = g_ilist[j + 3];
            acc += row[i0]; acc += row[i1]; acc += row[i2]; acc += row[i3];
        }
        for (; j < e; j++) acc += row[g_ilist[j]];
        g_syn_i[w * T_DATA + t0 + l] = acc;
    }
}

// ================= K2: grouped causal FIR, one (subunit, chunk) per block ==
// 128 threads x 8 outputs. One kv + one nv LDS.128 per 4-tap group feeds 32
// FMAs (2x arithmetic density vs 4-output version).
__global__ void __launch_bounds__(FIR_THREADS)
k_fir(void) {
    extern __shared__ float sh[];
    float* win = sh;                 // 2 * FIR_WIN  (e then i window)
    float* fk  = win + 2 * FIR_WIN;  // 2 * FKP

    const int s   = blockIdx.x % SUB_NO;
    const int t0  = (blockIdx.x / SUB_NO) * FIR_T;
    const int tid = threadIdx.x;

    // stage filters (e and i rows for this subunit)
    for (int q = tid; q < 2 * FKP / 4; q += FIR_THREADS) {
        int ch = q / (FKP / 4), r = q % (FKP / 4);
        ((float4*)&fk[ch * FKP])[r] = ((const float4*)&g_fk[(ch * SUB_NO + s) * FKP])[r];
    }

    // stage windows: win[ch][j] = syn[ch][s][t0-200+j], 0 outside [0,T_DATA)
    for (int q = tid; q < 2 * (FIR_WIN / 4); q += FIR_THREADS) {
        int ch = q / (FIR_WIN / 4), r = q % (FIR_WIN / 4);
        const float* src = ch ? g_syn_i : g_syn_e;
        int tb = t0 - 200 + 4 * r;       // multiple of 4
        float4 v;
        if (tb >= 0 && tb + 3 < T_DATA) {
            v = *(const float4*)&src[s * T_DATA + tb];
        } else {
            float x[4];
            #pragma unroll
            for (int k = 0; k < 4; k++) {
                int t = tb + k;
                x[k] = (t >= 0 && t < T_DATA) ? src[s * T_DATA + t] : 0.f;
            }
            v = make_float4(x[0], x[1], x[2], x[3]);
        }
        *(float4*)&win[ch * FIR_WIN + 4 * r] = v;
    }
    __syncthreads();

    float a0 = 0.f, a1 = 0.f, a2 = 0.f, a3 = 0.f;
    float a4 = 0.f, a5 = 0.f, a6 = 0.f, a7 = 0.f;
    #pragma unroll 1
    for (int ch = 0; ch < 2; ch++) {
        const float* wp = &win[ch * FIR_WIN + 8 * tid];
        const float* fp = &fk[ch * FKP];
        float4 v0 = *(const float4*)&wp[0];
        float4 v1 = *(const float4*)&wp[4];
        float b0 = v0.x, b1 = v0.y, b2 = v0.z, b3 = v0.w;
        float b4 = v1.x, b5 = v1.y, b6 = v1.z, b7 = v1.w;
        #pragma unroll 4
        for (int g = 0; g < NGROUP; g++) {
            float4 kv = *(const float4*)&fp[4 * g];       // broadcast LDS
            float4 nv = *(const float4*)&wp[4 * g + 8];
            a0 = fmaf(kv.x, b0, a0); a1 = fmaf(kv.x, b1, a1);
            a2 = fmaf(kv.x, b2, a2); a3 = fmaf(kv.x, b3, a3);
            a4 = fmaf(kv.x, b4, a4); a5 = fmaf(kv.x, b5, a5);
            a6 = fmaf(kv.x, b6, a6); a7 = fmaf(kv.x, b7, a7);
            a0 = fmaf(kv.y, b1, a0); a1 = fmaf(kv.y, b2, a1);
            a2 = fmaf(kv.y, b3, a2); a3 = fmaf(kv.y, b4, a3);
            a4 = fmaf(kv.y, b5, a4); a5 = fmaf(kv.y, b6, a5);
            a6 = fmaf(kv.y, b7, a6); a7 = fmaf(kv.y, nv.x, a7);
            a0 = fmaf(kv.z, b2, a0); a1 = fmaf(kv.z, b3, a1);
            a2 = fmaf(kv.z, b4, a2); a3 = fmaf(kv.z, b5, a3);
            a4 = fmaf(kv.z, b6, a4); a5 = fmaf(kv.z, b7, a5);
            a6 = fmaf(kv.z, nv.x, a6); a7 = fmaf(kv.z, nv.y, a7);
            a0 = fmaf(kv.w, b3, a0); a1 = fmaf(kv.w, b4, a1);
            a2 = fmaf(kv.w, b5, a2); a3 = fmaf(kv.w, b6, a3);
            a4 = fmaf(kv.w, b7, a4); a5 = fmaf(kv.w, nv.x, a5);
            a6 = fmaf(kv.w, nv.y, a6); a7 = fmaf(kv.w, nv.z, a7);
            b0 = b4; b1 = b5; b2 = b6; b3 = b7;
            b4 = nv.x; b5 = nv.y; b6 = nv.z; b7 = nv.w;
        }
    }
    int t = t0 + 8 * tid;
    if (t + 7 < T_DATA) {
        *(float4*)&g_fir[s * T_DATA + t]     = make_float4(a0, a1, a2, a3);
        *(float4*)&g_fir[s * T_DATA + t + 4] = make_float4(a4, a5, a6, a7);
    } else {
        float a[8] = {a0, a1, a2, a3, a4, a5, a6, a7};
        #pragma unroll
        for (int k = 0; k < 8; k++)
            if (t + k < T_DATA) g_fir[s * T_DATA + t + k] = a[k];
    }
}

// ================= K3: dendritic tree recursion (2 t per thread) ==========
__global__ void __launch_bounds__(TREE_THREADS)
k_tree(const float* __restrict__ C_den, const float* __restrict__ W_sub,
       const float* __restrict__ Theta, const float* __restrict__ V_o,
       const float* __restrict__ Cse, const float* __restrict__ Csi,
       float* __restrict__ out_v) {
    __shared__ float cw[SUB_NO * SUB_NO];
    __shared__ float th[SUB_NO];
    const int tid  = threadIdx.x;
    const int gidx = blockIdx.x * TREE_THREADS + tid;

    // fold the C_syn copies into this kernel (grid covers 50176 >= 20000)
    if (gidx < SUB_NO * E_NO) {
        out_v[T_DATA + 2 * SUB_NO * T_NO + gidx] = Cse[gidx];
    } else if (gidx < SUB_NO * E_NO + SUB_NO * I_NO) {
        int q = gidx - SUB_NO * E_NO;
        out_v[T_DATA + 2 * SUB_NO * T_NO + SUB_NO * E_NO + q] = Csi[q];
    }

    for (int idx = tid; idx < SUB_NO * SUB_NO; idx += TREE_THREADS) {
        int c = idx % SUB_NO;
        cw[idx] = C_den[idx] * expf(W_sub[c]);
    }
    if (tid < SUB_NO) th[tid] = Theta[tid];
    __syncthreads();

    const int t = gidx;
    if (t >= T_HALF) return;
    const float wexp0 = expf(W_sub[0]);
    const float vo    = V_o[0];

    float fA[SUB_NO], fB[SUB_NO];
    #pragma unroll
    for (int s = 0; s < SUB_NO; s++) {
        fA[s] = g_fir[s * T_DATA + t];
        fB[s] = g_fir[s * T_DATA + t + T_HALF];
    }
    float sA[SUB_NO], sB[SUB_NO];
    #pragma unroll
    for (int s = 0; s < SUB_NO; s++) { sA[s] = 0.f; sB[s] = 0.f; }
    #pragma unroll
    for (int s = SUB_NO - 1; s >= 0; s--) {
        float lA = 0.f, lB = 0.f;
        #pragma unroll
        for (int c = s + 1; c < SUB_NO; c++) {
            float w = cw[s * SUB_NO + c];
            lA = fmaf(w, sA[c], lA);
            lB = fmaf(w, sB[c], lB);
        }
        sA[s] = tanhf(fA[s] + lA + th[s]);
        sB[s] = tanhf(fB[s] + lB + th[s]);
    }
    out_v[t]          = sA[0] * wexp0 + vo;
    out_v[t + T_HALF] = sB[0] * wexp0 + vo;
}

// ============================= launch ======================================
extern "C" void kernel_launch(void* const* d_in, const int* in_sizes, int n_in,
                              void* d_out, int out_size) {
    const float* S_e   = (const float*)d_in[0];
    const float* S_i   = (const float*)d_in[1];
    const float* Cse   = (const float*)d_in[2];
    const float* Csi   = (const float*)d_in[3];
    const float* Cden  = (const float*)d_in[4];
    const float* Wsyn  = (const float*)d_in[5];
    const float* Tau   = (const float*)d_in[6];
    const float* Delta = (const float*)d_in[7];
    const float* Wsub  = (const float*)d_in[8];
    const float* Theta = (const float*)d_in[9];
    const float* Vo    = (const float*)d_in[10];
    float* out = (float*)d_out;

    cudaFuncSetAttribute(k_agg, cudaFuncAttributeMaxDynamicSharedMemorySize, AGG_SMEM);
    cudaFuncSetAttribute(k_fir, cudaFuncAttributeMaxDynamicSharedMemorySize, FIR_SMEM);

    // output layout: [0,100000) voltage | [100000,108040) filters |
    // [108040,124040) C_syn_e | [124040,128040) C_syn_i
    k_setup<<<1, 512>>>(Cse, Csi, Wsyn, Tau, Delta, out + T_DATA);
    k_agg<<<T_DATA / AGG_T, AGG_THREADS, AGG_SMEM>>>(S_e, S_i);
    k_fir<<<SUB_NO * FIR_CHUNKS, FIR_THREADS, FIR_SMEM>>>();
    k_tree<<<(T_HALF + TREE_THREADS - 1) / TREE_THREADS, TREE_THREADS>>>(
        Cden, Wsub, Theta, Vo, Cse, Csi, out);
}

// round 6
// speedup vs baseline: 2.1877x; 1.0334x over previous
#include <cuda_runtime.h>
#include <math.h>

#define SUB_NO 20
#define T_NO   201
#define T_DATA 100000
#define E_NO   800
#define I_NO   200

#define FKP     208            // flipped kernel row, padded (zeros at 201..207)
#define NGROUP  52             // FKP/4 tap groups
#define AGG_T   32             // t rows per aggregation tile
#define AGG_THREADS 640        // 20 warps (one per subunit)

#define FIR_T    1024          // outputs per fir block
#define FIR_THREADS 128        // 8 outputs/thread
#define FIR_WIN  1240          // 1024 + 200 halo + pad (310 float4)
#define FIR_CHUNKS ((T_DATA + FIR_T - 1) / FIR_T)   // 98

#define TREE_THREADS 256
#define T_HALF (T_DATA / 2)

#define AGG_SMEM  (32 * 801 * 4)
#define FIR_SMEM  ((2 * FIR_WIN + 2 * 2 * FKP) * 4)

typedef unsigned long long u64;

__device__ __forceinline__ u64 pk2(float lo, float hi) {
    u64 r; asm("mov.b64 %0, {%1, %2};" : "=l"(r) : "f"(lo), "f"(hi)); return r;
}
__device__ __forceinline__ void upk2(u64 p, float& lo, float& hi) {
    asm("mov.b64 {%0, %1}, %2;" : "=f"(lo), "=f"(hi) : "l"(p));
}
// packed dual fp32 fma: d = a*b + d  (SASS FFMA2, only reachable via PTX)
__device__ __forceinline__ void ffma2(u64& d, u64 a, u64 b) {
    asm("fma.rn.f32x2 %0, %1, %2, %0;" : "+l"(d) : "l"(a), "l"(b));
}

// -------- device scratch (no allocations allowed) --------
__device__ float g_syn_e[SUB_NO * T_DATA];
__device__ float g_syn_i[SUB_NO * T_DATA];
__device__ float g_fir[SUB_NO * T_DATA];
__device__ float g_fk [2 * SUB_NO * FKP];        // flipped taps
__device__ float g_fk2[2 * SUB_NO * 2 * FKP];    // flipped taps, each duplicated (k,k)
__device__ int   g_elist[E_NO];
__device__ int   g_ilist[I_NO];
__device__ int   g_eoff[SUB_NO + 1];
__device__ int   g_ioff[SUB_NO + 1];

// ================= K0: setup (lists, alpha kernels, filters out) ===========
__global__ void __launch_bounds__(512)
k_setup(const float* __restrict__ Cse, const float* __restrict__ Csi,
        const float* __restrict__ Wsyn, const float* __restrict__ Tau,
        const float* __restrict__ Delta,
        float* __restrict__ out_filters) {
    __shared__ int s_ae[E_NO];
    __shared__ int s_ai[I_NO];
    __shared__ int s_cnt_e[SUB_NO], s_cnt_i[SUB_NO];
    __shared__ int s_off_e[SUB_NO + 1], s_off_i[SUB_NO + 1];
    const int tid = threadIdx.x;

    // ---- alpha kernels ----
    for (int idx = tid; idx < 2 * SUB_NO * T_NO; idx += blockDim.x) {
        int t  = idx % T_NO;
        int sc = idx / T_NO;          // row of vstack: c*20 + s
        int c  = sc / SUB_NO;
        int s  = sc % SUB_NO;
        float v = 0.f;
        #pragma unroll
        for (int j = 0; j < 2; j++) {
            float W   = Wsyn [(s * 2 + j) * 2 + c];
            float tau = Tau  [(s * 2 + j) * 2 + c];
            float dl  = Delta[(s * 2 + j) * 2 + c];
            float td  = fmaxf((float)t - dl, 0.f);
            float tt  = td * expf(-tau);
            v += tt * expf(-tt) * W;
        }
        out_filters[sc * T_NO + t] = v;
        int u = T_NO - 1 - t;                 // flipped
        g_fk [sc * FKP + u] = v;
        g_fk2[sc * 2 * FKP + 2 * u]     = v;
        g_fk2[sc * 2 * FKP + 2 * u + 1] = v;
    }
    for (int idx = tid; idx < 2 * SUB_NO * (FKP - T_NO); idx += blockDim.x) {
        int sc = idx / (FKP - T_NO);
        int p  = idx % (FKP - T_NO);
        int u  = T_NO + p;
        g_fk [sc * FKP + u] = 0.f;
        g_fk2[sc * 2 * FKP + 2 * u]     = 0.f;
        g_fk2[sc * 2 * FKP + 2 * u + 1] = 0.f;
    }

    // ---- assignments + counts ----
    if (tid < SUB_NO) { s_cnt_e[tid] = 0; s_cnt_i[tid] = 0; }
    __syncthreads();
    for (int e = tid; e < E_NO; e += blockDim.x) {
        int a = 0;
        #pragma unroll
        for (int s = 0; s < SUB_NO; s++) a += s * (Cse[s * E_NO + e] > 0.5f);
        s_ae[e] = a;
        atomicAdd(&s_cnt_e[a], 1);
    }
    for (int i = tid; i < I_NO; i += blockDim.x) {
        int a = 0;
        #pragma unroll
        for (int s = 0; s < SUB_NO; s++) a += s * (Csi[s * I_NO + i] > 0.5f);
        s_ai[i] = a;
        atomicAdd(&s_cnt_i[a], 1);
    }
    __syncthreads();
    if (tid == 0) {
        int acc = 0;
        for (int s = 0; s < SUB_NO; s++) { s_off_e[s] = acc; acc += s_cnt_e[s]; }
        s_off_e[SUB_NO] = acc;
        acc = 0;
        for (int s = 0; s < SUB_NO; s++) { s_off_i[s] = acc; acc += s_cnt_i[s]; }
        s_off_i[SUB_NO] = acc;
    }
    __syncthreads();
    // ---- deterministic parallel scatter via rank ----
    for (int e = tid; e < E_NO; e += blockDim.x) {
        int a = s_ae[e], r = 0;
        for (int p = 0; p < e; p++) r += (s_ae[p] == a);
        g_elist[s_off_e[a] + r] = e;
    }
    for (int i = tid; i < I_NO; i += blockDim.x) {
        int a = s_ai[i], r = 0;
        for (int p = 0; p < i; p++) r += (s_ai[p] == a);
        g_ilist[s_off_i[a] + r] = i;
    }
    if (tid <= SUB_NO) { g_eoff[tid] = s_off_e[tid]; g_ioff[tid] = s_off_i[tid]; }
}

// ================= K1: one-hot aggregation (segmented sum) ================
__global__ void __launch_bounds__(AGG_THREADS)
k_agg(const float* __restrict__ S_e, const float* __restrict__ S_i) {
    extern __shared__ float sh[];
    const int t0  = blockIdx.x * AGG_T;
    const int tid = threadIdx.x;
    const int w   = tid >> 5;      // warp = subunit
    const int l   = tid & 31;      // lane = t within tile

    // ---- excitatory: 32 x 800 tile, row stride 801 (conflict-free both ways)
    {
        const float4* src = (const float4*)S_e;
        int r = tid / 200, c = tid % 200;      // once; then incremental
        #pragma unroll
        for (int j = 0; j < 10; j++) {         // 6400 float4 / 640 threads
            float4 v = src[(size_t)(t0 + r) * 200 + c];
            float* d = &sh[r * 801 + 4 * c];
            d[0] = v.x; d[1] = v.y; d[2] = v.z; d[3] = v.w;
            r += 3; c += 40; if (c >= 200) { c -= 200; r++; }
        }
    }
    __syncthreads();
    {
        int b = g_eoff[w], e = g_eoff[w + 1];
        const float* row = &sh[l * 801];
        float acc = 0.f;
        int j = b;
        for (; j + 4 <= e; j += 4) {
            int i0 = g_elist[j], i1 = g_elist[j + 1], i2 = g_elist[j + 2], i3 = g_elist[j + 3];
            acc += row[i0]; acc += row[i1]; acc += row[i2]; acc += row[i3];
        }
        for (; j < e; j++) acc += row[g_elist[j]];
        g_syn_e[w * T_DATA + t0 + l] = acc;
    }
    __syncthreads();
    // ---- inhibitory: 32 x 200 tile, row stride 201 (conflict-free)
    {
        const float4* src = (const float4*)S_i;
        int r = tid / 50, c = tid % 50;
        #pragma unroll
        for (int j = 0; j < 3; j++) {          // 1600 float4; last pass partial
            if (j < 2 || tid < 320) {
                float4 v = src[(size_t)(t0 + r) * 50 + c];
                float* d = &sh[r * 201 + 4 * c];
                d[0] = v.x; d[1] = v.y; d[2] = v.z; d[3] = v.w;
            }
            r += 12; c += 40; if (c >= 50) { c -= 50; r++; }
        }
    }
    __syncthreads();
    {
        int b = g_ioff[w], e = g_ioff[w + 1];
        const float* row = &sh[l * 201];
        float acc = 0.f;
        int j = b;
        for (; j + 4 <= e; j += 4) {
            int i0 = g_ilist[j], i1 = g_ilist[j + 1], i2 = g_ilist[j + 2], i3 = g_ilist[j + 3];
            acc += row[i0]; acc += row[i1]; acc += row[i2]; acc += row[i3];
        }
        for (; j < e; j++) acc += row[g_ilist[j]];
        g_syn_i[w * T_DATA + t0 + l] = acc;
    }
}

// ================= K2: grouped causal FIR with packed f32x2 FMA ===========
// 128 threads x 8 outputs. Pairs at output-stride 4: A_m=(a_m,a_{m+4}),
// window packs P_j=(b_j,b_{j+4}) -> every tap offset hits an existing pack.
// Filter taps duplicated in smem so LDS.128 yields ready (k,k) operands.
__global__ void __launch_bounds__(FIR_THREADS)
k_fir(void) {
    extern __shared__ float sh[];
    float* win = sh;                   // 2 * FIR_WIN  (e then i window)
    float* fkd = win + 2 * FIR_WIN;    // 2 * 2*FKP duplicated taps

    const int s   = blockIdx.x % SUB_NO;
    const int t0  = (blockIdx.x / SUB_NO) * FIR_T;
    const int tid = threadIdx.x;

    // stage duplicated filters (e and i rows for this subunit)
    for (int q = tid; q < 2 * 2 * FKP / 4; q += FIR_THREADS) {
        int ch = q / (2 * FKP / 4), r = q % (2 * FKP / 4);
        ((float4*)&fkd[ch * 2 * FKP])[r] =
            ((const float4*)&g_fk2[(ch * SUB_NO + s) * 2 * FKP])[r];
    }

    // stage windows: win[ch][j] = syn[ch][s][t0-200+j], 0 outside [0,T_DATA)
    for (int q = tid; q < 2 * (FIR_WIN / 4); q += FIR_THREADS) {
        int ch = q / (FIR_WIN / 4), r = q % (FIR_WIN / 4);
        const float* src = ch ? g_syn_i : g_syn_e;
        int tb = t0 - 200 + 4 * r;       // multiple of 4
        float4 v;
        if (tb >= 0 && tb + 3 < T_DATA) {
            v = *(const float4*)&src[s * T_DATA + tb];
        } else {
            float x[4];
            #pragma unroll
            for (int k = 0; k < 4; k++) {
                int t = tb + k;
                x[k] = (t >= 0 && t < T_DATA) ? src[s * T_DATA + t] : 0.f;
            }
            v = make_float4(x[0], x[1], x[2], x[3]);
        }
        *(float4*)&win[ch * FIR_WIN + 4 * r] = v;
    }
    __syncthreads();

    u64 A0 = 0, A1 = 0, A2 = 0, A3 = 0;   // bit pattern (0.f, 0.f)
    #pragma unroll 1
    for (int ch = 0; ch < 2; ch++) {
        const float* wp = &win[ch * FIR_WIN + 8 * tid];
        const float* fd = &fkd[ch * 2 * FKP];
        float4 v0 = *(const float4*)&wp[0];
        float4 v1 = *(const float4*)&wp[4];
        float4 v2 = *(const float4*)&wp[8];
        u64 P0 = pk2(v0.x, v1.x), P1 = pk2(v0.y, v1.y);
        u64 P2 = pk2(v0.z, v1.z), P3 = pk2(v0.w, v1.w);
        u64 P4 = pk2(v1.x, v2.x), P5 = pk2(v1.y, v2.y);
        u64 P6 = pk2(v1.z, v2.z), P7 = pk2(v1.w, v2.w);
        #pragma unroll 4
        for (int g = 0; g < NGROUP - 1; g++) {
            const ulonglong2* kd = (const ulonglong2*)&fd[8 * g];
            ulonglong2 k01 = kd[0];      // (kx,kx) (ky,ky)
            ulonglong2 k23 = kd[1];      // (kz,kz) (kw,kw)
            ffma2(A0, k01.x, P0); ffma2(A1, k01.x, P1);
            ffma2(A2, k01.x, P2); ffma2(A3, k01.x, P3);
            ffma2(A0, k01.y, P1); ffma2(A1, k01.y, P2);
            ffma2(A2, k01.y, P3); ffma2(A3, k01.y, P4);
            ffma2(A0, k23.x, P2); ffma2(A1, k23.x, P3);
            ffma2(A2, k23.x, P4); ffma2(A3, k23.x, P5);
            ffma2(A0, k23.y, P3); ffma2(A1, k23.y, P4);
            ffma2(A2, k23.y, P5); ffma2(A3, k23.y, P6);
            // slide window by 4: P_j <- P_{j+4}; new hi halves from nv
            float4 nv = *(const float4*)&wp[4 * g + 12];
            float lo, h4, h5, h6, h7;
            upk2(P4, lo, h4); upk2(P5, lo, h5);
            upk2(P6, lo, h6); upk2(P7, lo, h7);
            P0 = P4; P1 = P5; P2 = P6; P3 = P7;
            P4 = pk2(h4, nv.x); P5 = pk2(h5, nv.y);
            P6 = pk2(h6, nv.z); P7 = pk2(h7, nv.w);
        }
        {   // last group: no slide needed
            const ulonglong2* kd = (const ulonglong2*)&fd[8 * (NGROUP - 1)];
            ulonglong2 k01 = kd[0];
            ulonglong2 k23 = kd[1];
            ffma2(A0, k01.x, P0); ffma2(A1, k01.x, P1);
            ffma2(A2, k01.x, P2); ffma2(A3, k01.x, P3);
            ffma2(A0, k01.y, P1); ffma2(A1, k01.y, P2);
            ffma2(A2, k01.y, P3); ffma2(A3, k01.y, P4);
            ffma2(A0, k23.x, P2); ffma2(A1, k23.x, P3);
            ffma2(A2, k23.x, P4); ffma2(A3, k23.x, P5);
            ffma2(A0, k23.y, P3); ffma2(A1, k23.y, P4);
            ffma2(A2, k23.y, P5); ffma2(A3, k23.y, P6);
        }
    }
    float a0, a1, a2, a3, a4, a5, a6, a7;
    upk2(A0, a0, a4); upk2(A1, a1, a5);
    upk2(A2, a2, a6); upk2(A3, a3, a7);

    int t = t0 + 8 * tid;
    if (t + 7 < T_DATA) {
        *(float4*)&g_fir[s * T_DATA + t]     = make_float4(a0, a1, a2, a3);
        *(float4*)&g_fir[s * T_DATA + t + 4] = make_float4(a4, a5, a6, a7);
    } else {
        float a[8] = {a0, a1, a2, a3, a4, a5, a6, a7};
        #pragma unroll
        for (int k = 0; k < 8; k++)
            if (t + k < T_DATA) g_fir[s * T_DATA + t + k] = a[k];
    }
}

// ================= K3: dendritic tree recursion (2 t per thread) ==========
__global__ void __launch_bounds__(TREE_THREADS)
k_tree(const float* __restrict__ C_den, const float* __restrict__ W_sub,
       const float* __restrict__ Theta, const float* __restrict__ V_o,
       const float* __restrict__ Cse, const float* __restrict__ Csi,
       float* __restrict__ out_v) {
    __shared__ float cw[SUB_NO * SUB_NO];
    __shared__ float th[SUB_NO];
    const int tid  = threadIdx.x;
    const int gidx = blockIdx.x * TREE_THREADS + tid;

    // fold the C_syn copies into this kernel (grid covers 50176 >= 20000)
    if (gidx < SUB_NO * E_NO) {
        out_v[T_DATA + 2 * SUB_NO * T_NO + gidx] = Cse[gidx];
    } else if (gidx < SUB_NO * E_NO + SUB_NO * I_NO) {
        int q = gidx - SUB_NO * E_NO;
        out_v[T_DATA + 2 * SUB_NO * T_NO + SUB_NO * E_NO + q] = Csi[q];
    }

    for (int idx = tid; idx < SUB_NO * SUB_NO; idx += TREE_THREADS) {
        int c = idx % SUB_NO;
        cw[idx] = C_den[idx] * expf(W_sub[c]);
    }
    if (tid < SUB_NO) th[tid] = Theta[tid];
    __syncthreads();

    const int t = gidx;
    if (t >= T_HALF) return;
    const float wexp0 = expf(W_sub[0]);
    const float vo    = V_o[0];

    float fA[SUB_NO], fB[SUB_NO];
    #pragma unroll
    for (int s = 0; s < SUB_NO; s++) {
        fA[s] = g_fir[s * T_DATA + t];
        fB[s] = g_fir[s * T_DATA + t + T_HALF];
    }
    float sA[SUB_NO], sB[SUB_NO];
    #pragma unroll
    for (int s = 0; s < SUB_NO; s++) { sA[s] = 0.f; sB[s] = 0.f; }
    #pragma unroll
    for (int s = SUB_NO - 1; s >= 0; s--) {
        float lA = 0.f, lB = 0.f;
        #pragma unroll
        for (int c = s + 1; c < SUB_NO; c++) {
            float w = cw[s * SUB_NO + c];
            lA = fmaf(w, sA[c], lA);
            lB = fmaf(w, sB[c], lB);
        }
        sA[s] = tanhf(fA[s] + lA + th[s]);
        sB[s] = tanhf(fB[s] + lB + th[s]);
    }
    out_v[t]          = sA[0] * wexp0 + vo;
    out_v[t + T_HALF] = sB[0] * wexp0 + vo;
}

// ============================= launch ======================================
extern "C" void kernel_launch(void* const* d_in, const int* in_sizes, int n_in,
                              void* d_out, int out_size) {
    const float* S_e   = (const float*)d_in[0];
    const float* S_i   = (const float*)d_in[1];
    const float* Cse   = (const float*)d_in[2];
    const float* Csi   = (const float*)d_in[3];
    const float* Cden  = (const float*)d_in[4];
    const float* Wsyn  = (const float*)d_in[5];
    const float* Tau   = (const float*)d_in[6];
    const float* Delta = (const float*)d_in[7];
    const float* Wsub  = (const float*)d_in[8];
    const float* Theta = (const float*)d_in[9];
    const float* Vo    = (const float*)d_in[10];
    float* out = (float*)d_out;

    cudaFuncSetAttribute(k_agg, cudaFuncAttributeMaxDynamicSharedMemorySize, AGG_SMEM);
    cudaFuncSetAttribute(k_fir, cudaFuncAttributeMaxDynamicSharedMemorySize, FIR_SMEM);

    // output layout: [0,100000) voltage | [100000,108040) filters |
    // [108040,124040) C_syn_e | [124040,128040) C_syn_i
    k_setup<<<1, 512>>>(Cse, Csi, Wsyn, Tau, Delta, out + T_DATA);
    k_agg<<<T_DATA / AGG_T, AGG_THREADS, AGG_SMEM>>>(S_e, S_i);
    k_fir<<<SUB_NO * FIR_CHUNKS, FIR_THREADS, FIR_SMEM>>>();
    k_tree<<<(T_HALF + TREE_THREADS - 1) / TREE_THREADS, TREE_THREADS>>>(
        Cden, Wsub, Theta, Vo, Cse, Csi, out);
}

// round 7
// speedup vs baseline: 2.2207x; 1.0151x over previous
#include <cuda_runtime.h>
#include <math.h>

#define SUB_NO 20
#define T_NO   201
#define T_DATA 100000
#define E_NO   800
#define I_NO   200

#define FKP     208            // flipped kernel row, padded (zeros at 201..207)
#define NGROUP  52             // FKP/4 tap groups

#define AGG_T   16             // t rows per aggregation tile
#define AGG_THREADS 640        // 20 warps (one per subunit, half-warp list split)
#define AGG_BLOCKS (T_DATA / AGG_T)   // 6250

#define FIR_T    1024          // outputs per fir block
#define FIR_THREADS 128        // 8 outputs/thread
#define FIR_WIN  1240          // 1024 + 200 halo + pad (310 float4)
#define FIR_CHUNKS ((T_DATA + FIR_T - 1) / FIR_T)   // 98

#define TREE_THREADS 256

// e-tile 16x801 + i-tile 16x201 floats
#define AGG_SMEM  ((AGG_T * 801 + AGG_T * 201) * 4)
#define FIR_SMEM  ((FIR_WIN + 2 * FKP) * 4)

typedef unsigned long long u64;

__device__ __forceinline__ u64 pk2(float lo, float hi) {
    u64 r; asm("mov.b64 %0, {%1, %2};" : "=l"(r) : "f"(lo), "f"(hi)); return r;
}
__device__ __forceinline__ void upk2(u64 p, float& lo, float& hi) {
    asm("mov.b64 {%0, %1}, %2;" : "=f"(lo), "=f"(hi) : "l"(p));
}
// packed dual fp32 fma: d = a*b + d  (SASS FFMA2)
__device__ __forceinline__ void ffma2(u64& d, u64 a, u64 b) {
    asm("fma.rn.f32x2 %0, %1, %2, %0;" : "+l"(d) : "l"(a), "l"(b));
}

// -------- device scratch (no allocations allowed) --------
__device__ float g_syn_e[SUB_NO * T_DATA];
__device__ float g_syn_i[SUB_NO * T_DATA];
__device__ float g_fir_e[SUB_NO * T_DATA];
__device__ float g_fir_i[SUB_NO * T_DATA];
__device__ float g_fk2[2 * SUB_NO * 2 * FKP];    // flipped taps, duplicated (k,k)
__device__ int   g_elist[E_NO];
__device__ int   g_ilist[I_NO];
__device__ int   g_eoff[SUB_NO + 1];
__device__ int   g_ioff[SUB_NO + 1];

// ================= K0: setup (lists, alpha kernels, filters out) ===========
__global__ void __launch_bounds__(512)
k_setup(const float* __restrict__ Cse, const float* __restrict__ Csi,
        const float* __restrict__ Wsyn, const float* __restrict__ Tau,
        const float* __restrict__ Delta,
        float* __restrict__ out_filters) {
    __shared__ int s_ae[E_NO];
    __shared__ int s_ai[I_NO];
    __shared__ int s_cnt_e[SUB_NO], s_cnt_i[SUB_NO];
    __shared__ int s_off_e[SUB_NO + 1], s_off_i[SUB_NO + 1];
    const int tid = threadIdx.x;

    // ---- alpha kernels ----
    for (int idx = tid; idx < 2 * SUB_NO * T_NO; idx += blockDim.x) {
        int t  = idx % T_NO;
        int sc = idx / T_NO;          // row of vstack: c*20 + s
        int c  = sc / SUB_NO;
        int s  = sc % SUB_NO;
        float v = 0.f;
        #pragma unroll
        for (int j = 0; j < 2; j++) {
            float W   = Wsyn [(s * 2 + j) * 2 + c];
            float tau = Tau  [(s * 2 + j) * 2 + c];
            float dl  = Delta[(s * 2 + j) * 2 + c];
            float td  = fmaxf((float)t - dl, 0.f);
            float tt  = td * expf(-tau);
            v += tt * expf(-tt) * W;
        }
        out_filters[sc * T_NO + t] = v;
        int u = T_NO - 1 - t;                 // flipped
        g_fk2[sc * 2 * FKP + 2 * u]     = v;
        g_fk2[sc * 2 * FKP + 2 * u + 1] = v;
    }
    for (int idx = tid; idx < 2 * SUB_NO * (FKP - T_NO); idx += blockDim.x) {
        int sc = idx / (FKP - T_NO);
        int p  = idx % (FKP - T_NO);
        int u  = T_NO + p;
        g_fk2[sc * 2 * FKP + 2 * u]     = 0.f;
        g_fk2[sc * 2 * FKP + 2 * u + 1] = 0.f;
    }

    // ---- assignments + counts ----
    if (tid < SUB_NO) { s_cnt_e[tid] = 0; s_cnt_i[tid] = 0; }
    __syncthreads();
    for (int e = tid; e < E_NO; e += blockDim.x) {
        int a = 0;
        #pragma unroll
        for (int s = 0; s < SUB_NO; s++) a += s * (Cse[s * E_NO + e] > 0.5f);
        s_ae[e] = a;
        atomicAdd(&s_cnt_e[a], 1);
    }
    for (int i = tid; i < I_NO; i += blockDim.x) {
        int a = 0;
        #pragma unroll
        for (int s = 0; s < SUB_NO; s++) a += s * (Csi[s * I_NO + i] > 0.5f);
        s_ai[i] = a;
        atomicAdd(&s_cnt_i[a], 1);
    }
    __syncthreads();
    if (tid == 0) {
        int acc = 0;
        for (int s = 0; s < SUB_NO; s++) { s_off_e[s] = acc; acc += s_cnt_e[s]; }
        s_off_e[SUB_NO] = acc;
        acc = 0;
        for (int s = 0; s < SUB_NO; s++) { s_off_i[s] = acc; acc += s_cnt_i[s]; }
        s_off_i[SUB_NO] = acc;
    }
    __syncthreads();
    // ---- deterministic parallel scatter via rank ----
    for (int e = tid; e < E_NO; e += blockDim.x) {
        int a = s_ae[e], r = 0;
        for (int p = 0; p < e; p++) r += (s_ae[p] == a);
        g_elist[s_off_e[a] + r] = e;
    }
    for (int i = tid; i < I_NO; i += blockDim.x) {
        int a = s_ai[i], r = 0;
        for (int p = 0; p < i; p++) r += (s_ai[p] == a);
        g_ilist[s_off_i[a] + r] = i;
    }
    if (tid <= SUB_NO) { g_eoff[tid] = s_off_e[tid]; g_ioff[tid] = s_off_i[tid]; }
}

// ================= K1: one-hot aggregation (segmented sum) ================
// AGG_T=16 rows/tile -> 64KB smem -> 3 blocks/SM (phase overlap keeps HBM busy).
// warp = subunit; lanes 0-15 sum even list entries (row = lane), lanes 16-31
// odd entries (same rows); combine via shfl_down(16). i-tile LDGs issued
// before the e-gather so they complete underneath it.
__global__ void __launch_bounds__(AGG_THREADS)
k_agg(const float* __restrict__ S_e, const float* __restrict__ S_i) {
    extern __shared__ float sh[];
    float* she = sh;                     // 16 x 801
    float* shi = sh + AGG_T * 801;       // 16 x 201
    const int t0  = blockIdx.x * AGG_T;
    const int tid = threadIdx.x;
    const int w   = tid >> 5;            // warp = subunit
    const int l   = tid & 31;
    const int lr  = l & 15;              // row within tile

    // ---- load e-tile: 16 x 200 float4, 5 per thread
    float4 ev[5];
    {
        const float4* src = (const float4*)S_e;
        int r = tid / 200, c = tid % 200;
        int rr[5], cc[5];
        #pragma unroll
        for (int j = 0; j < 5; j++) {
            rr[j] = r; cc[j] = c;
            ev[j] = src[(size_t)(t0 + r) * 200 + c];
            r += 3; c += 40; if (c >= 200) { c -= 200; r++; }
        }
        #pragma unroll
        for (int j = 0; j < 5; j++) {
            float* d = &she[rr[j] * 801 + 4 * cc[j]];
            d[0] = ev[j].x; d[1] = ev[j].y; d[2] = ev[j].z; d[3] = ev[j].w;
        }
    }
    // ---- issue i-tile loads now (land during e-gather): 16 x 50 float4
    float4 iv0, iv1;
    int ir0, ic0, ir1 = 0, ic1 = 0;
    {
        const float4* src = (const float4*)S_i;
        ir0 = tid / 50; ic0 = tid % 50;
        iv0 = src[(size_t)(t0 + ir0) * 50 + ic0];
        if (tid < 160) {
            ir1 = (tid + 640) / 50; ic1 = (tid + 640) % 50;
            iv1 = src[(size_t)(t0 + ir1) * 50 + ic1];
        }
    }
    __syncthreads();
    // ---- e-gather
    {
        int b = g_eoff[w], e = g_eoff[w + 1];
        const float* row = &she[lr * 801];
        float acc = 0.f;
        int j = b + (l >> 4);            // lo lanes even entries, hi lanes odd
        for (; j + 2 < e; j += 4) {      // 2-wide ILP
            acc += row[g_elist[j]];
            acc += row[g_elist[j + 2]];
        }
        if (j < e) acc += row[g_elist[j]];
        acc += __shfl_down_sync(0xffffffffu, acc, 16);
        if (l < 16) g_syn_e[w * T_DATA + t0 + lr] = acc;
    }
    __syncthreads();
    // ---- store i-tile
    {
        float* d = &shi[ir0 * 201 + 4 * ic0];
        d[0] = iv0.x; d[1] = iv0.y; d[2] = iv0.z; d[3] = iv0.w;
        if (tid < 160) {
            float* d2 = &shi[ir1 * 201 + 4 * ic1];
            d2[0] = iv1.x; d2[1] = iv1.y; d2[2] = iv1.z; d2[3] = iv1.w;
        }
    }
    __syncthreads();
    // ---- i-gather
    {
        int b = g_ioff[w], e = g_ioff[w + 1];
        const float* row = &shi[lr * 201];
        float acc = 0.f;
        int j = b + (l >> 4);
        for (; j + 2 < e; j += 4) {
            acc += row[g_ilist[j]];
            acc += row[g_ilist[j + 2]];
        }
        if (j < e) acc += row[g_ilist[j]];
        acc += __shfl_down_sync(0xffffffffu, acc, 16);
        if (l < 16) g_syn_i[w * T_DATA + t0 + lr] = acc;
    }
}

// ================= K2: grouped causal FIR, one (ch, subunit, chunk)/block ==
// 128 threads x 8 outputs, packed f32x2 FMA; single channel per block.
__global__ void __launch_bounds__(FIR_THREADS)
k_fir(void) {
    extern __shared__ float sh[];
    float* win = sh;                   // FIR_WIN
    float* fkd = win + FIR_WIN;        // 2*FKP duplicated taps

    const int bid   = blockIdx.x;
    const int s     = bid % SUB_NO;
    const int chunk = (bid / SUB_NO) % FIR_CHUNKS;
    const int ch    = bid / (SUB_NO * FIR_CHUNKS);
    const int t0    = chunk * FIR_T;
    const int tid   = threadIdx.x;

    const float* src = ch ? g_syn_i : g_syn_e;
    float*       dst = ch ? g_fir_i : g_fir_e;

    // stage duplicated filters for this (ch, s)
    for (int q = tid; q < 2 * FKP / 4; q += FIR_THREADS)
        ((float4*)fkd)[q] = ((const float4*)&g_fk2[(ch * SUB_NO + s) * 2 * FKP])[q];

    // stage window: win[j] = src[s][t0-200+j], 0 outside [0,T_DATA)
    for (int r = tid; r < FIR_WIN / 4; r += FIR_THREADS) {
        int tb = t0 - 200 + 4 * r;       // multiple of 4
        float4 v;
        if (tb >= 0 && tb + 3 < T_DATA) {
            v = *(const float4*)&src[s * T_DATA + tb];
        } else {
            float x[4];
            #pragma unroll
            for (int k = 0; k < 4; k++) {
                int t = tb + k;
                x[k] = (t >= 0 && t < T_DATA) ? src[s * T_DATA + t] : 0.f;
            }
            v = make_float4(x[0], x[1], x[2], x[3]);
        }
        *(float4*)&win[4 * r] = v;
    }
    __syncthreads();

    u64 A0 = 0, A1 = 0, A2 = 0, A3 = 0;   // (0.f,0.f) pairs, outputs stride 4
    {
        const float* wp = &win[8 * tid];
        float4 v0 = *(const float4*)&wp[0];
        float4 v1 = *(const float4*)&wp[4];
        float4 v2 = *(const float4*)&wp[8];
        u64 P0 = pk2(v0.x, v1.x), P1 = pk2(v0.y, v1.y);
        u64 P2 = pk2(v0.z, v1.z), P3 = pk2(v0.w, v1.w);
        u64 P4 = pk2(v1.x, v2.x), P5 = pk2(v1.y, v2.y);
        u64 P6 = pk2(v1.z, v2.z), P7 = pk2(v1.w, v2.w);
        #pragma unroll 4
        for (int g = 0; g < NGROUP - 1; g++) {
            const ulonglong2* kd = (const ulonglong2*)&fkd[8 * g];
            ulonglong2 k01 = kd[0];      // (kx,kx) (ky,ky)
            ulonglong2 k23 = kd[1];      // (kz,kz) (kw,kw)
            ffma2(A0, k01.x, P0); ffma2(A1, k01.x, P1);
            ffma2(A2, k01.x, P2); ffma2(A3, k01.x, P3);
            ffma2(A0, k01.y, P1); ffma2(A1, k01.y, P2);
            ffma2(A2, k01.y, P3); ffma2(A3, k01.y, P4);
            ffma2(A0, k23.x, P2); ffma2(A1, k23.x, P3);
            ffma2(A2, k23.x, P4); ffma2(A3, k23.x, P5);
            ffma2(A0, k23.y, P3); ffma2(A1, k23.y, P4);
            ffma2(A2, k23.y, P5); ffma2(A3, k23.y, P6);
            // slide window by 4
            float4 nv = *(const float4*)&wp[4 * g + 12];
            float lo, h4, h5, h6, h7;
            upk2(P4, lo, h4); upk2(P5, lo, h5);
            upk2(P6, lo, h6); upk2(P7, lo, h7);
            P0 = P4; P1 = P5; P2 = P6; P3 = P7;
            P4 = pk2(h4, nv.x); P5 = pk2(h5, nv.y);
            P6 = pk2(h6, nv.z); P7 = pk2(h7, nv.w);
        }
        {   // last group
            const ulonglong2* kd = (const ulonglong2*)&fkd[8 * (NGROUP - 1)];
            ulonglong2 k01 = kd[0];
            ulonglong2 k23 = kd[1];
            ffma2(A0, k01.x, P0); ffma2(A1, k01.x, P1);
            ffma2(A2, k01.x, P2); ffma2(A3, k01.x, P3);
            ffma2(A0, k01.y, P1); ffma2(A1, k01.y, P2);
            ffma2(A2, k01.y, P3); ffma2(A3, k01.y, P4);
            ffma2(A0, k23.x, P2); ffma2(A1, k23.x, P3);
            ffma2(A2, k23.x, P4); ffma2(A3, k23.x, P5);
            ffma2(A0, k23.y, P3); ffma2(A1, k23.y, P4);
            ffma2(A2, k23.y, P5); ffma2(A3, k23.y, P6);
        }
    }
    float a0, a1, a2, a3, a4, a5, a6, a7;
    upk2(A0, a0, a4); upk2(A1, a1, a5);
    upk2(A2, a2, a6); upk2(A3, a3, a7);

    int t = t0 + 8 * tid;
    if (t + 7 < T_DATA) {
        *(float4*)&dst[s * T_DATA + t]     = make_float4(a0, a1, a2, a3);
        *(float4*)&dst[s * T_DATA + t + 4] = make_float4(a4, a5, a6, a7);
    } else {
        float a[8] = {a0, a1, a2, a3, a4, a5, a6, a7};
        #pragma unroll
        for (int k = 0; k < 8; k++)
            if (t + k < T_DATA) dst[s * T_DATA + t + k] = a[k];
    }
}

// ================= K3: dendritic tree recursion (1 t per thread) ==========
__global__ void __launch_bounds__(TREE_THREADS)
k_tree(const float* __restrict__ C_den, const float* __restrict__ W_sub,
       const float* __restrict__ Theta, const float* __restrict__ V_o,
       const float* __restrict__ Cse, const float* __restrict__ Csi,
       float* __restrict__ out_v) {
    __shared__ float cw[SUB_NO * SUB_NO];
    __shared__ float th[SUB_NO];
    const int tid  = threadIdx.x;
    const int gidx = blockIdx.x * TREE_THREADS + tid;

    // fold the C_syn copies into this kernel (grid covers 100096 >= 20000)
    if (gidx < SUB_NO * E_NO) {
        out_v[T_DATA + 2 * SUB_NO * T_NO + gidx] = Cse[gidx];
    } else if (gidx < SUB_NO * E_NO + SUB_NO * I_NO) {
        int q = gidx - SUB_NO * E_NO;
        out_v[T_DATA + 2 * SUB_NO * T_NO + SUB_NO * E_NO + q] = Csi[q];
    }

    for (int idx = tid; idx < SUB_NO * SUB_NO; idx += TREE_THREADS) {
        int c = idx % SUB_NO;
        cw[idx] = C_den[idx] * expf(W_sub[c]);
    }
    if (tid < SUB_NO) th[tid] = Theta[tid];
    __syncthreads();

    const int t = gidx;
    if (t >= T_DATA) return;

    float f[SUB_NO];
    #pragma unroll
    for (int s = 0; s < SUB_NO; s++)
        f[s] = g_fir_e[s * T_DATA + t] + g_fir_i[s * T_DATA + t];

    float sub[SUB_NO];
    #pragma unroll
    for (int s = 0; s < SUB_NO; s++) sub[s] = 0.f;
    #pragma unroll
    for (int s = SUB_NO - 1; s >= 0; s--) {
        float leaf = 0.f;
        #pragma unroll
        for (int c = s + 1; c < SUB_NO; c++)
            leaf = fmaf(cw[s * SUB_NO + c], sub[c], leaf);
        sub[s] = tanhf(f[s] + leaf + th[s]);
    }
    out_v[t] = sub[0] * expf(W_sub[0]) + V_o[0];
}

// ============================= launch ======================================
extern "C" void kernel_launch(void* const* d_in, const int* in_sizes, int n_in,
                              void* d_out, int out_size) {
    const float* S_e   = (const float*)d_in[0];
    const float* S_i   = (const float*)d_in[1];
    const float* Cse   = (const float*)d_in[2];
    const float* Csi   = (const float*)d_in[3];
    const float* Cden  = (const float*)d_in[4];
    const float* Wsyn  = (const float*)d_in[5];
    const float* Tau   = (const float*)d_in[6];
    const float* Delta = (const float*)d_in[7];
    const float* Wsub  = (const float*)d_in[8];
    const float* Theta = (const float*)d_in[9];
    const float* Vo    = (const float*)d_in[10];
    float* out = (float*)d_out;

    cudaFuncSetAttribute(k_agg, cudaFuncAttributeMaxDynamicSharedMemorySize, AGG_SMEM);
    cudaFuncSetAttribute(k_fir, cudaFuncAttributeMaxDynamicSharedMemorySize, FIR_SMEM);

    // output layout: [0,100000) voltage | [100000,108040) filters |
    // [108040,124040) C_syn_e | [124040,128040) C_syn_i
    k_setup<<<1, 512>>>(Cse, Csi, Wsyn, Tau, Delta, out + T_DATA);
    k_agg<<<AGG_BLOCKS, AGG_THREADS, AGG_SMEM>>>(S_e, S_i);
    k_fir<<<2 * SUB_NO * FIR_CHUNKS, FIR_THREADS, FIR_SMEM>>>();
    k_tree<<<(T_DATA + TREE_THREADS - 1) / TREE_THREADS, TREE_THREADS>>>(
        Cden, Wsub, Theta, Vo, Cse, Csi, out);
}